// round 2
// baseline (speedup 1.0000x reference)
#include <cuda_runtime.h>
#include <cuda_bf16.h>
#include <math.h>

#define N_NODES 100000
#define E_EDGES 3200000
#define F 256
#define NOUT 128

// ---------------- scratch (device globals; no allocation allowed) ----------
__device__ float g_S [N_NODES * F];   // support = x @ W_nb
__device__ float g_A [N_NODES * F];   // accumulator: x@W_self + b, then += spmm
__device__ float g_X1[N_NODES * F];   // x after layer-1 relu
__device__ float g_g1[N_NODES];
__device__ float g_g2[N_NODES];
__device__ float g_r [N_NODES];
__device__ float g_z [N_NODES];
__device__ float g_part[512 * 4];     // per-block (m1,s1,m2,s2)
__device__ float g_stat[4];           // m1,s1,m2,s2
__device__ float g_colsum[F];

#define NEG_BIG (-3.0e38f)

// ---------------- small utility kernels ----------------
__global__ void k_zero_colsum() {
    if (threadIdx.x < F) g_colsum[threadIdx.x] = 0.0f;
}

// ---------------- SGEMM: C[M,256] = (A (*rvec rowscale)) @ W[256,256] (+bias) ----
#define BM 128
#define BN 128
#define BK 16

__global__ __launch_bounds__(256) void k_gemm(
    const float* __restrict__ A, const float* __restrict__ W,
    const float* __restrict__ bias, float* __restrict__ C,
    const float* __restrict__ rvec, int M)
{
    __shared__ float As[BK][BM + 4];   // stride 132: 2-way max conflicts on transpose store
    __shared__ float Bs[BK][BN];

    const int tid = threadIdx.x;
    const int tx = tid & 15;          // 0..15 -> col group
    const int ty = tid >> 4;          // 0..15 -> row group
    const int rowBlock = blockIdx.x * BM;
    const int colBlock = blockIdx.y * BN;

    float acc[8][8];
    #pragma unroll
    for (int i = 0; i < 8; i++)
        #pragma unroll
        for (int j = 0; j < 8; j++) acc[i][j] = 0.0f;

    for (int k0 = 0; k0 < F; k0 += BK) {
        // load A tile: 128 rows x 16 k (transpose into As[k][row])
        #pragma unroll
        for (int it = 0; it < 2; it++) {
            int idx = tid + it * 256;           // 0..511
            int r   = idx >> 2;                 // row in tile
            int k4  = (idx & 3) << 2;           // 0,4,8,12
            int grow = rowBlock + r;
            float4 v = make_float4(0.f, 0.f, 0.f, 0.f);
            if (grow < M) {
                v = *reinterpret_cast<const float4*>(&A[(size_t)grow * F + k0 + k4]);
                if (rvec) {
                    float rr = rvec[grow];
                    v.x *= rr; v.y *= rr; v.z *= rr; v.w *= rr;
                }
            }
            As[k4 + 0][r] = v.x;
            As[k4 + 1][r] = v.y;
            As[k4 + 2][r] = v.z;
            As[k4 + 3][r] = v.w;
        }
        // load W tile: 16 k x 128 n
        #pragma unroll
        for (int it = 0; it < 2; it++) {
            int idx = tid + it * 256;           // 0..511
            int kr  = idx >> 5;                 // 0..15
            int nc  = (idx & 31) << 2;          // 0..124
            float4 v = *reinterpret_cast<const float4*>(&W[(size_t)(k0 + kr) * F + colBlock + nc]);
            *reinterpret_cast<float4*>(&Bs[kr][nc]) = v;
        }
        __syncthreads();

        #pragma unroll
        for (int k = 0; k < BK; k++) {
            float4 a0 = *reinterpret_cast<const float4*>(&As[k][ty * 8]);
            float4 a1 = *reinterpret_cast<const float4*>(&As[k][ty * 8 + 4]);
            float4 b0 = *reinterpret_cast<const float4*>(&Bs[k][tx * 8]);
            float4 b1 = *reinterpret_cast<const float4*>(&Bs[k][tx * 8 + 4]);
            float am[8] = {a0.x, a0.y, a0.z, a0.w, a1.x, a1.y, a1.z, a1.w};
            float bn[8] = {b0.x, b0.y, b0.z, b0.w, b1.x, b1.y, b1.z, b1.w};
            #pragma unroll
            for (int i = 0; i < 8; i++)
                #pragma unroll
                for (int j = 0; j < 8; j++)
                    acc[i][j] += am[i] * bn[j];
        }
        __syncthreads();
    }

    float bv[8];
    #pragma unroll
    for (int j = 0; j < 8; j++)
        bv[j] = bias ? bias[colBlock + tx * 8 + j] : 0.0f;

    #pragma unroll
    for (int i = 0; i < 8; i++) {
        int grow = rowBlock + ty * 8 + i;
        if (grow < M) {
            float* cp = &C[(size_t)grow * F + colBlock + tx * 8];
            float4 o0 = make_float4(acc[i][0] + bv[0], acc[i][1] + bv[1],
                                    acc[i][2] + bv[2], acc[i][3] + bv[3]);
            float4 o1 = make_float4(acc[i][4] + bv[4], acc[i][5] + bv[5],
                                    acc[i][6] + bv[6], acc[i][7] + bv[7]);
            *reinterpret_cast<float4*>(cp)     = o0;
            *reinterpret_cast<float4*>(cp + 4) = o1;
        }
    }
}

// ---------------- SpMM via vector atomics: A[row] += val * S[col] --------------
__global__ void k_spmm(const int* __restrict__ er, const int* __restrict__ ec,
                       const float* __restrict__ ev)
{
    int warp = (blockIdx.x * blockDim.x + threadIdx.x) >> 5;
    int lane = threadIdx.x & 31;
    if (warp >= E_EDGES) return;
    int row = er[warp];
    int col = ec[warp];
    float v = ev[warp];
    const float4* S4 = reinterpret_cast<const float4*>(g_S) + (size_t)col * 64;
    float4*       A4 = reinterpret_cast<float4*>(g_A)       + (size_t)row * 64;
    #pragma unroll
    for (int j = 0; j < 2; j++) {
        float4 s = __ldg(&S4[lane + 32 * j]);
        s.x *= v; s.y *= v; s.z *= v; s.w *= v;
        atomicAdd(&A4[lane + 32 * j], s);   // sm_90+ float4 RED
    }
}

// ---------------- relu(A)->X1 and gate dot products -----------------------
__global__ void k_relu_gates(const float* __restrict__ w1, const float* __restrict__ b1g,
                             const float* __restrict__ w2, const float* __restrict__ b2g)
{
    int warp = (blockIdx.x * blockDim.x + threadIdx.x) >> 5;
    int lane = threadIdx.x & 31;
    if (warp >= N_NODES) return;
    const float4* A4 = reinterpret_cast<const float4*>(g_A) + (size_t)warp * 64;
    float4*       X4 = reinterpret_cast<float4*>(g_X1)      + (size_t)warp * 64;
    const float4* W1 = reinterpret_cast<const float4*>(w1);
    const float4* W2 = reinterpret_cast<const float4*>(w2);
    float d1 = 0.f, d2 = 0.f;
    #pragma unroll
    for (int j = 0; j < 2; j++) {
        int idx = lane + 32 * j;
        float4 a = A4[idx];
        a.x = fmaxf(a.x, 0.f); a.y = fmaxf(a.y, 0.f);
        a.z = fmaxf(a.z, 0.f); a.w = fmaxf(a.w, 0.f);
        X4[idx] = a;
        float4 u = W1[idx];
        float4 t = W2[idx];
        d1 += a.x * u.x + a.y * u.y + a.z * u.z + a.w * u.w;
        d2 += a.x * t.x + a.y * t.y + a.z * t.z + a.w * t.w;
    }
    #pragma unroll
    for (int off = 16; off; off >>= 1) {
        d1 += __shfl_xor_sync(0xffffffffu, d1, off);
        d2 += __shfl_xor_sync(0xffffffffu, d2, off);
    }
    if (lane == 0) {
        g_g1[warp] = d1 + b1g[0];
        g_g2[warp] = d2 + b2g[0];
    }
}

// ---------------- softmax over nodes: online (max, sumexp) -----------------
__device__ __forceinline__ void merge_ms(float& m, float& s, float mb, float sb) {
    float M = fmaxf(m, mb);
    s = s * __expf(m - M) + sb * __expf(mb - M);
    m = M;
}

__global__ void k_softmax_part()
{
    float m1 = NEG_BIG, s1 = 0.f, m2 = NEG_BIG, s2 = 0.f;
    for (int i = blockIdx.x * blockDim.x + threadIdx.x; i < N_NODES;
         i += gridDim.x * blockDim.x) {
        float v1 = g_g1[i];
        merge_ms(m1, s1, v1, 1.0f);
        float v2 = g_g2[i];
        merge_ms(m2, s2, v2, 1.0f);
    }
    __shared__ float sm1[256], ss1[256], sm2[256], ss2[256];
    int t = threadIdx.x;
    sm1[t] = m1; ss1[t] = s1; sm2[t] = m2; ss2[t] = s2;
    __syncthreads();
    for (int off = 128; off; off >>= 1) {
        if (t < off) {
            float mm = sm1[t], ss = ss1[t];
            merge_ms(mm, ss, sm1[t + off], ss1[t + off]);
            sm1[t] = mm; ss1[t] = ss;
            mm = sm2[t]; ss = ss2[t];
            merge_ms(mm, ss, sm2[t + off], ss2[t + off]);
            sm2[t] = mm; ss2[t] = ss;
        }
        __syncthreads();
    }
    if (t == 0) {
        g_part[blockIdx.x * 4 + 0] = sm1[0];
        g_part[blockIdx.x * 4 + 1] = ss1[0];
        g_part[blockIdx.x * 4 + 2] = sm2[0];
        g_part[blockIdx.x * 4 + 3] = ss2[0];
    }
}

__global__ void k_softmax_final(int nparts)
{
    __shared__ float sm1[128], ss1[128], sm2[128], ss2[128];
    int t = threadIdx.x;
    float m1 = NEG_BIG, s1 = 0.f, m2 = NEG_BIG, s2 = 0.f;
    if (t < nparts) {
        m1 = g_part[t * 4 + 0]; s1 = g_part[t * 4 + 1];
        m2 = g_part[t * 4 + 2]; s2 = g_part[t * 4 + 3];
    }
    sm1[t] = m1; ss1[t] = s1; sm2[t] = m2; ss2[t] = s2;
    __syncthreads();
    for (int off = 64; off; off >>= 1) {
        if (t < off) {
            float mm = sm1[t], ss = ss1[t];
            merge_ms(mm, ss, sm1[t + off], ss1[t + off]);
            sm1[t] = mm; ss1[t] = ss;
            mm = sm2[t]; ss = ss2[t];
            merge_ms(mm, ss, sm2[t + off], ss2[t + off]);
            sm2[t] = mm; ss2[t] = ss;
        }
        __syncthreads();
    }
    if (t == 0) {
        g_stat[0] = sm1[0]; g_stat[1] = ss1[0];
        g_stat[2] = sm2[0]; g_stat[3] = ss2[0];
    }
}

__global__ void k_rz()
{
    int i = blockIdx.x * blockDim.x + threadIdx.x;
    if (i < N_NODES) {
        g_r[i] = __expf(g_g1[i] - g_stat[0]) / g_stat[1];
        g_z[i] = __expf(g_g2[i] - g_stat[2]) / g_stat[3];
    }
}

// ---------------- final mix + column-sum --------------------------------
__global__ void k_mix(float* __restrict__ out)
{
    int f = threadIdx.x;                   // 256 threads = 1 feature each
    float local = 0.f;
    for (int row = blockIdx.x; row < N_NODES; row += gridDim.x) {
        float z  = g_z[row];
        float a  = g_A [(size_t)row * F + f];
        float x1 = g_X1[(size_t)row * F + f];
        float xe = (1.f - z) * x1 + z * fmaxf(a, 0.f);
        out[(size_t)row * F + f] = xe;
        local += xe;
    }
    atomicAdd(&g_colsum[f], local);
}

__global__ void k_out(const float* __restrict__ e2pw, const float* __restrict__ e2pb,
                      float* __restrict__ out)
{
    __shared__ float mean[F];
    for (int i = threadIdx.x; i < F; i += blockDim.x)
        mean[i] = g_colsum[i] * (1.0f / N_NODES);
    __syncthreads();
    int j = threadIdx.x;
    if (j < NOUT) {
        float acc = e2pb[j];
        #pragma unroll 8
        for (int k = 0; k < F; k++)
            acc += mean[k] * e2pw[(size_t)k * NOUT + j];
        out[(size_t)N_NODES * F + j] = acc;
    }
}

// ---------------- launch ----------------
extern "C" void kernel_launch(void* const* d_in, const int* in_sizes, int n_in,
                              void* d_out, int out_size)
{
    const float* inputs  = (const float*)d_in[0];
    const int*   er      = (const int*)  d_in[1];
    const int*   ec      = (const int*)  d_in[2];
    const float* ev      = (const float*)d_in[3];
    const float* W_self1 = (const float*)d_in[4];
    const float* W_nb1   = (const float*)d_in[5];
    const float* b1      = (const float*)d_in[6];
    const float* W_self2 = (const float*)d_in[7];
    const float* W_nb2   = (const float*)d_in[8];
    const float* b2      = (const float*)d_in[9];
    const float* g1w     = (const float*)d_in[10];
    const float* g1b     = (const float*)d_in[11];
    const float* g2w     = (const float*)d_in[12];
    const float* g2b     = (const float*)d_in[13];
    const float* e2pw    = (const float*)d_in[14];
    const float* e2pb    = (const float*)d_in[15];
    float* out = (float*)d_out;

    float *pA, *pS, *pX1, *pR;
    cudaGetSymbolAddress((void**)&pA,  g_A);
    cudaGetSymbolAddress((void**)&pS,  g_S);
    cudaGetSymbolAddress((void**)&pX1, g_X1);
    cudaGetSymbolAddress((void**)&pR,  g_r);

    dim3 gg((N_NODES + BM - 1) / BM, F / BN);   // (782, 2)

    k_zero_colsum<<<1, 256>>>();

    // ---- layer 1 ----
    k_gemm<<<gg, 256>>>(inputs, W_self1, b1,      pA, nullptr, N_NODES);
    k_gemm<<<gg, 256>>>(inputs, W_nb1,   nullptr, pS, nullptr, N_NODES);
    k_spmm<<<E_EDGES / 8, 256>>>(er, ec, ev);
    k_relu_gates<<<N_NODES / 8, 256>>>(g1w, g1b, g2w, g2b);

    // ---- softmax gates over nodes ----
    k_softmax_part<<<120, 256>>>();
    k_softmax_final<<<1, 128>>>(120);
    k_rz<<<(N_NODES + 255) / 256, 256>>>();

    // ---- layer 2 (rows of X1 scaled by r) ----
    k_gemm<<<gg, 256>>>(pX1, W_self2, b2,      pA, pR, N_NODES);
    k_gemm<<<gg, 256>>>(pX1, W_nb2,   nullptr, pS, pR, N_NODES);
    k_spmm<<<E_EDGES / 8, 256>>>(er, ec, ev);

    // ---- mix, mean, head ----
    k_mix<<<512, 256>>>(out);
    k_out<<<1, 128>>>(e2pw, e2pb, out);
}

// round 3
// speedup vs baseline: 1.5048x; 1.5048x over previous
#include <cuda_runtime.h>
#include <cuda_bf16.h>
#include <math.h>

#define N_NODES 100000
#define E_EDGES 3200000
#define F 256
#define NOUT 128

#define SCAN_BLK 256
#define SCAN_NBLK ((N_NODES + SCAN_BLK - 1) / SCAN_BLK)   // 391

// ---------------- scratch (device globals; no allocation allowed) ----------
__device__ float g_S [N_NODES * F];   // support = x @ W_nb
__device__ float g_A [N_NODES * F];   // accumulator: x@W_self + b, then += spmm
__device__ float g_X1[N_NODES * F];   // x after layer-1 relu
__device__ float g_g1[N_NODES];
__device__ float g_g2[N_NODES];
__device__ float g_r [N_NODES];
__device__ float g_z [N_NODES];
__device__ float g_part[512 * 4];
__device__ float g_stat[4];
__device__ float g_colsum[F];

// CSR scratch
__device__ int   g_cnt[N_NODES];      // histogram, then reused as scatter cursor
__device__ int   g_rowptr[N_NODES + 1];
__device__ int   g_bsum[SCAN_NBLK];
__device__ int   g_boff[SCAN_NBLK];
__device__ int   g_csr_col[E_EDGES];
__device__ float g_csr_val[E_EDGES];

#define NEG_BIG (-3.0e38f)

// ---------------- small utility kernels ----------------
__global__ void k_zero_colsum() {
    if (threadIdx.x < F) g_colsum[threadIdx.x] = 0.0f;
}

__global__ void k_zero_cnt() {
    int i = blockIdx.x * blockDim.x + threadIdx.x;
    if (i < N_NODES) g_cnt[i] = 0;
}

// ---------------- CSR build ------------------------------------------------
__global__ void k_hist(const int* __restrict__ er) {
    int i = blockIdx.x * blockDim.x + threadIdx.x;
    if (i < E_EDGES) atomicAdd(&g_cnt[er[i]], 1);
}

__device__ __forceinline__ int warp_scan_incl(int v, int lane) {
    #pragma unroll
    for (int off = 1; off < 32; off <<= 1) {
        int t = __shfl_up_sync(0xffffffffu, v, off);
        if (lane >= off) v += t;
    }
    return v;
}

// block-level exclusive scan of g_cnt tiles -> g_rowptr, block totals -> g_bsum
__global__ void k_scan1() {
    __shared__ int wsum[8];
    int t = threadIdx.x;
    int lane = t & 31, wid = t >> 5;
    int i = blockIdx.x * SCAN_BLK + t;
    int v = (i < N_NODES) ? g_cnt[i] : 0;
    int incl = warp_scan_incl(v, lane);
    if (lane == 31) wsum[wid] = incl;
    __syncthreads();
    if (wid == 0) {
        int s = (lane < 8) ? wsum[lane] : 0;
        s = warp_scan_incl(s, lane);
        if (lane < 8) wsum[lane] = s;
    }
    __syncthreads();
    int off = wid ? wsum[wid - 1] : 0;
    incl += off;
    if (i < N_NODES) g_rowptr[i] = incl - v;    // exclusive within block
    if (t == SCAN_BLK - 1) g_bsum[blockIdx.x] = incl;
}

// exclusive scan of the 391 block sums (single block of 512)
__global__ void k_scan2() {
    __shared__ int wsum[16];
    int t = threadIdx.x;
    int lane = t & 31, wid = t >> 5;
    int v = (t < SCAN_NBLK) ? g_bsum[t] : 0;
    int incl = warp_scan_incl(v, lane);
    if (lane == 31) wsum[wid] = incl;
    __syncthreads();
    if (wid == 0) {
        int s = (lane < 16) ? wsum[lane] : 0;
        s = warp_scan_incl(s, lane);
        if (lane < 16) wsum[lane] = s;
    }
    __syncthreads();
    int off = wid ? wsum[wid - 1] : 0;
    incl += off;
    if (t < SCAN_NBLK) g_boff[t] = incl - v;
}

__global__ void k_scan3() {
    int i = blockIdx.x * blockDim.x + threadIdx.x;
    if (i < N_NODES) {
        int val = g_rowptr[i] + g_boff[i >> 8];
        g_rowptr[i] = val;
        g_cnt[i] = val;                 // scatter cursor
    }
    if (i == 0) g_rowptr[N_NODES] = E_EDGES;
}

__global__ void k_scatter(const int* __restrict__ er, const int* __restrict__ ec,
                          const float* __restrict__ ev) {
    int i = blockIdx.x * blockDim.x + threadIdx.x;
    if (i < E_EDGES) {
        int row = er[i];
        int pos = atomicAdd(&g_cnt[row], 1);
        g_csr_col[pos] = ec[i];
        g_csr_val[pos] = ev[i];
    }
}

// ---------------- SGEMM: C[M,256] = (A (*rvec rowscale)) @ W[256,256] (+bias) ----
#define BM 128
#define BN 128
#define BK 16

__global__ __launch_bounds__(256) void k_gemm(
    const float* __restrict__ A, const float* __restrict__ W,
    const float* __restrict__ bias, float* __restrict__ C,
    const float* __restrict__ rvec, int M)
{
    __shared__ float As[BK][BM + 4];
    __shared__ float Bs[BK][BN];

    const int tid = threadIdx.x;
    const int tx = tid & 15;
    const int ty = tid >> 4;
    const int rowBlock = blockIdx.x * BM;
    const int colBlock = blockIdx.y * BN;

    float acc[8][8];
    #pragma unroll
    for (int i = 0; i < 8; i++)
        #pragma unroll
        for (int j = 0; j < 8; j++) acc[i][j] = 0.0f;

    for (int k0 = 0; k0 < F; k0 += BK) {
        #pragma unroll
        for (int it = 0; it < 2; it++) {
            int idx = tid + it * 256;
            int r   = idx >> 2;
            int k4  = (idx & 3) << 2;
            int grow = rowBlock + r;
            float4 v = make_float4(0.f, 0.f, 0.f, 0.f);
            if (grow < M) {
                v = *reinterpret_cast<const float4*>(&A[(size_t)grow * F + k0 + k4]);
                if (rvec) {
                    float rr = rvec[grow];
                    v.x *= rr; v.y *= rr; v.z *= rr; v.w *= rr;
                }
            }
            As[k4 + 0][r] = v.x;
            As[k4 + 1][r] = v.y;
            As[k4 + 2][r] = v.z;
            As[k4 + 3][r] = v.w;
        }
        #pragma unroll
        for (int it = 0; it < 2; it++) {
            int idx = tid + it * 256;
            int kr  = idx >> 5;
            int nc  = (idx & 31) << 2;
            float4 v = *reinterpret_cast<const float4*>(&W[(size_t)(k0 + kr) * F + colBlock + nc]);
            *reinterpret_cast<float4*>(&Bs[kr][nc]) = v;
        }
        __syncthreads();

        #pragma unroll
        for (int k = 0; k < BK; k++) {
            float4 a0 = *reinterpret_cast<const float4*>(&As[k][ty * 8]);
            float4 a1 = *reinterpret_cast<const float4*>(&As[k][ty * 8 + 4]);
            float4 b0 = *reinterpret_cast<const float4*>(&Bs[k][tx * 8]);
            float4 b1 = *reinterpret_cast<const float4*>(&Bs[k][tx * 8 + 4]);
            float am[8] = {a0.x, a0.y, a0.z, a0.w, a1.x, a1.y, a1.z, a1.w};
            float bn[8] = {b0.x, b0.y, b0.z, b0.w, b1.x, b1.y, b1.z, b1.w};
            #pragma unroll
            for (int i = 0; i < 8; i++)
                #pragma unroll
                for (int j = 0; j < 8; j++)
                    acc[i][j] += am[i] * bn[j];
        }
        __syncthreads();
    }

    float bv[8];
    #pragma unroll
    for (int j = 0; j < 8; j++)
        bv[j] = bias ? bias[colBlock + tx * 8 + j] : 0.0f;

    #pragma unroll
    for (int i = 0; i < 8; i++) {
        int grow = rowBlock + ty * 8 + i;
        if (grow < M) {
            float* cp = &C[(size_t)grow * F + colBlock + tx * 8];
            float4 o0 = make_float4(acc[i][0] + bv[0], acc[i][1] + bv[1],
                                    acc[i][2] + bv[2], acc[i][3] + bv[3]);
            float4 o1 = make_float4(acc[i][4] + bv[4], acc[i][5] + bv[5],
                                    acc[i][6] + bv[6], acc[i][7] + bv[7]);
            *reinterpret_cast<float4*>(cp)     = o0;
            *reinterpret_cast<float4*>(cp + 4) = o1;
        }
    }
}

// ---------------- CSR SpMM: one warp per row, register accumulators ----------
__device__ __forceinline__ void fma4(float4& a, float v, const float4& s) {
    a.x = fmaf(v, s.x, a.x);
    a.y = fmaf(v, s.y, a.y);
    a.z = fmaf(v, s.z, a.z);
    a.w = fmaf(v, s.w, a.w);
}

__global__ __launch_bounds__(256) void k_spmm_csr()
{
    int warp = (blockIdx.x * blockDim.x + threadIdx.x) >> 5;
    int lane = threadIdx.x & 31;
    if (warp >= N_NODES) return;
    int s = g_rowptr[warp];
    int e = g_rowptr[warp + 1];

    const float4* S4 = reinterpret_cast<const float4*>(g_S);
    float4 a0 = make_float4(0.f, 0.f, 0.f, 0.f);
    float4 a1 = make_float4(0.f, 0.f, 0.f, 0.f);

    int i = s;
    for (; i + 1 < e; i += 2) {
        int   c0 = g_csr_col[i];
        int   c1 = g_csr_col[i + 1];
        float v0 = g_csr_val[i];
        float v1 = g_csr_val[i + 1];
        const float4* p0 = S4 + (size_t)c0 * 64;
        const float4* p1 = S4 + (size_t)c1 * 64;
        float4 s00 = __ldg(p0 + lane);
        float4 s01 = __ldg(p0 + 32 + lane);
        float4 s10 = __ldg(p1 + lane);
        float4 s11 = __ldg(p1 + 32 + lane);
        fma4(a0, v0, s00); fma4(a1, v0, s01);
        fma4(a0, v1, s10); fma4(a1, v1, s11);
    }
    if (i < e) {
        int   c0 = g_csr_col[i];
        float v0 = g_csr_val[i];
        const float4* p0 = S4 + (size_t)c0 * 64;
        float4 s00 = __ldg(p0 + lane);
        float4 s01 = __ldg(p0 + 32 + lane);
        fma4(a0, v0, s00); fma4(a1, v0, s01);
    }

    float4* A4 = reinterpret_cast<float4*>(g_A) + (size_t)warp * 64;
    float4 d0 = A4[lane];
    float4 d1 = A4[lane + 32];
    d0.x += a0.x; d0.y += a0.y; d0.z += a0.z; d0.w += a0.w;
    d1.x += a1.x; d1.y += a1.y; d1.z += a1.z; d1.w += a1.w;
    A4[lane]      = d0;
    A4[lane + 32] = d1;
}

// ---------------- relu(A)->X1 and gate dot products -----------------------
__global__ void k_relu_gates(const float* __restrict__ w1, const float* __restrict__ b1g,
                             const float* __restrict__ w2, const float* __restrict__ b2g)
{
    int warp = (blockIdx.x * blockDim.x + threadIdx.x) >> 5;
    int lane = threadIdx.x & 31;
    if (warp >= N_NODES) return;
    const float4* A4 = reinterpret_cast<const float4*>(g_A) + (size_t)warp * 64;
    float4*       X4 = reinterpret_cast<float4*>(g_X1)      + (size_t)warp * 64;
    const float4* W1 = reinterpret_cast<const float4*>(w1);
    const float4* W2 = reinterpret_cast<const float4*>(w2);
    float d1 = 0.f, d2 = 0.f;
    #pragma unroll
    for (int j = 0; j < 2; j++) {
        int idx = lane + 32 * j;
        float4 a = A4[idx];
        a.x = fmaxf(a.x, 0.f); a.y = fmaxf(a.y, 0.f);
        a.z = fmaxf(a.z, 0.f); a.w = fmaxf(a.w, 0.f);
        X4[idx] = a;
        float4 u = W1[idx];
        float4 t = W2[idx];
        d1 += a.x * u.x + a.y * u.y + a.z * u.z + a.w * u.w;
        d2 += a.x * t.x + a.y * t.y + a.z * t.z + a.w * t.w;
    }
    #pragma unroll
    for (int off = 16; off; off >>= 1) {
        d1 += __shfl_xor_sync(0xffffffffu, d1, off);
        d2 += __shfl_xor_sync(0xffffffffu, d2, off);
    }
    if (lane == 0) {
        g_g1[warp] = d1 + b1g[0];
        g_g2[warp] = d2 + b2g[0];
    }
}

// ---------------- softmax over nodes: online (max, sumexp) -----------------
__device__ __forceinline__ void merge_ms(float& m, float& s, float mb, float sb) {
    float M = fmaxf(m, mb);
    s = s * __expf(m - M) + sb * __expf(mb - M);
    m = M;
}

__global__ void k_softmax_part()
{
    float m1 = NEG_BIG, s1 = 0.f, m2 = NEG_BIG, s2 = 0.f;
    for (int i = blockIdx.x * blockDim.x + threadIdx.x; i < N_NODES;
         i += gridDim.x * blockDim.x) {
        float v1 = g_g1[i];
        merge_ms(m1, s1, v1, 1.0f);
        float v2 = g_g2[i];
        merge_ms(m2, s2, v2, 1.0f);
    }
    __shared__ float sm1[256], ss1[256], sm2[256], ss2[256];
    int t = threadIdx.x;
    sm1[t] = m1; ss1[t] = s1; sm2[t] = m2; ss2[t] = s2;
    __syncthreads();
    for (int off = 128; off; off >>= 1) {
        if (t < off) {
            float mm = sm1[t], ss = ss1[t];
            merge_ms(mm, ss, sm1[t + off], ss1[t + off]);
            sm1[t] = mm; ss1[t] = ss;
            mm = sm2[t]; ss = ss2[t];
            merge_ms(mm, ss, sm2[t + off], ss2[t + off]);
            sm2[t] = mm; ss2[t] = ss;
        }
        __syncthreads();
    }
    if (t == 0) {
        g_part[blockIdx.x * 4 + 0] = sm1[0];
        g_part[blockIdx.x * 4 + 1] = ss1[0];
        g_part[blockIdx.x * 4 + 2] = sm2[0];
        g_part[blockIdx.x * 4 + 3] = ss2[0];
    }
}

__global__ void k_softmax_final(int nparts)
{
    __shared__ float sm1[128], ss1[128], sm2[128], ss2[128];
    int t = threadIdx.x;
    float m1 = NEG_BIG, s1 = 0.f, m2 = NEG_BIG, s2 = 0.f;
    if (t < nparts) {
        m1 = g_part[t * 4 + 0]; s1 = g_part[t * 4 + 1];
        m2 = g_part[t * 4 + 2]; s2 = g_part[t * 4 + 3];
    }
    sm1[t] = m1; ss1[t] = s1; sm2[t] = m2; ss2[t] = s2;
    __syncthreads();
    for (int off = 64; off; off >>= 1) {
        if (t < off) {
            float mm = sm1[t], ss = ss1[t];
            merge_ms(mm, ss, sm1[t + off], ss1[t + off]);
            sm1[t] = mm; ss1[t] = ss;
            mm = sm2[t]; ss = ss2[t];
            merge_ms(mm, ss, sm2[t + off], ss2[t + off]);
            sm2[t] = mm; ss2[t] = ss;
        }
        __syncthreads();
    }
    if (t == 0) {
        g_stat[0] = sm1[0]; g_stat[1] = ss1[0];
        g_stat[2] = sm2[0]; g_stat[3] = ss2[0];
    }
}

__global__ void k_rz()
{
    int i = blockIdx.x * blockDim.x + threadIdx.x;
    if (i < N_NODES) {
        g_r[i] = __expf(g_g1[i] - g_stat[0]) / g_stat[1];
        g_z[i] = __expf(g_g2[i] - g_stat[2]) / g_stat[3];
    }
}

// ---------------- final mix + column-sum --------------------------------
__global__ void k_mix(float* __restrict__ out)
{
    int f = threadIdx.x;
    float local = 0.f;
    for (int row = blockIdx.x; row < N_NODES; row += gridDim.x) {
        float z  = g_z[row];
        float a  = g_A [(size_t)row * F + f];
        float x1 = g_X1[(size_t)row * F + f];
        float xe = (1.f - z) * x1 + z * fmaxf(a, 0.f);
        out[(size_t)row * F + f] = xe;
        local += xe;
    }
    atomicAdd(&g_colsum[f], local);
}

__global__ void k_out(const float* __restrict__ e2pw, const float* __restrict__ e2pb,
                      float* __restrict__ out)
{
    __shared__ float mean[F];
    for (int i = threadIdx.x; i < F; i += blockDim.x)
        mean[i] = g_colsum[i] * (1.0f / N_NODES);
    __syncthreads();
    int j = threadIdx.x;
    if (j < NOUT) {
        float acc = e2pb[j];
        #pragma unroll 8
        for (int k = 0; k < F; k++)
            acc += mean[k] * e2pw[(size_t)k * NOUT + j];
        out[(size_t)N_NODES * F + j] = acc;
    }
}

// ---------------- launch ----------------
extern "C" void kernel_launch(void* const* d_in, const int* in_sizes, int n_in,
                              void* d_out, int out_size)
{
    const float* inputs  = (const float*)d_in[0];
    const int*   er      = (const int*)  d_in[1];
    const int*   ec      = (const int*)  d_in[2];
    const float* ev      = (const float*)d_in[3];
    const float* W_self1 = (const float*)d_in[4];
    const float* W_nb1   = (const float*)d_in[5];
    const float* b1      = (const float*)d_in[6];
    const float* W_self2 = (const float*)d_in[7];
    const float* W_nb2   = (const float*)d_in[8];
    const float* b2      = (const float*)d_in[9];
    const float* g1w     = (const float*)d_in[10];
    const float* g1b     = (const float*)d_in[11];
    const float* g2w     = (const float*)d_in[12];
    const float* g2b     = (const float*)d_in[13];
    const float* e2pw    = (const float*)d_in[14];
    const float* e2pb    = (const float*)d_in[15];
    float* out = (float*)d_out;

    float *pA, *pS, *pX1, *pR;
    cudaGetSymbolAddress((void**)&pA,  g_A);
    cudaGetSymbolAddress((void**)&pS,  g_S);
    cudaGetSymbolAddress((void**)&pX1, g_X1);
    cudaGetSymbolAddress((void**)&pR,  g_r);

    dim3 gg((N_NODES + BM - 1) / BM, F / BN);   // (782, 2)
    const int EB = (E_EDGES + 255) / 256;
    const int NB = (N_NODES + 255) / 256;

    k_zero_colsum<<<1, 256>>>();

    // ---- CSR build (shared by both SpMMs) ----
    k_zero_cnt<<<NB, 256>>>();
    k_hist<<<EB, 256>>>(er);
    k_scan1<<<SCAN_NBLK, SCAN_BLK>>>();
    k_scan2<<<1, 512>>>();
    k_scan3<<<NB, 256>>>();
    k_scatter<<<EB, 256>>>(er, ec, ev);

    // ---- layer 1 ----
    k_gemm<<<gg, 256>>>(inputs, W_self1, b1,      pA, nullptr, N_NODES);
    k_gemm<<<gg, 256>>>(inputs, W_nb1,   nullptr, pS, nullptr, N_NODES);
    k_spmm_csr<<<(N_NODES * 32 + 255) / 256, 256>>>();
    k_relu_gates<<<N_NODES / 8, 256>>>(g1w, g1b, g2w, g2b);

    // ---- softmax gates over nodes ----
    k_softmax_part<<<120, 256>>>();
    k_softmax_final<<<1, 128>>>(120);
    k_rz<<<NB, 256>>>();

    // ---- layer 2 (rows of X1 scaled by r) ----
    k_gemm<<<gg, 256>>>(pX1, W_self2, b2,      pA, pR, N_NODES);
    k_gemm<<<gg, 256>>>(pX1, W_nb2,   nullptr, pS, pR, N_NODES);
    k_spmm_csr<<<(N_NODES * 32 + 255) / 256, 256>>>();

    // ---- mix, mean, head ----
    k_mix<<<512, 256>>>(out);
    k_out<<<1, 128>>>(e2pw, e2pb, out);
}

// round 5
// speedup vs baseline: 2.1443x; 1.4249x over previous
#include <cuda_runtime.h>
#include <cuda_bf16.h>
#include <math.h>
#include <stdint.h>

#define N_NODES 100000
#define E_EDGES 3200000
#define F 256
#define NOUT 128

#define SCAN_BLK 256
#define SCAN_NBLK ((N_NODES + SCAN_BLK - 1) / SCAN_BLK)   // 391

// ---------------- scratch (device globals; no allocation allowed) ----------
__device__ float g_S [N_NODES * F];   // support = x @ W_nb
__device__ float g_A [N_NODES * F];   // accumulator: x@W_self + b, then += spmm
__device__ float g_X1[N_NODES * F];   // x after layer-1 relu
__device__ float g_g1[N_NODES];
__device__ float g_g2[N_NODES];
__device__ float g_r [N_NODES];
__device__ float g_z [N_NODES];
__device__ float g_part[512 * 4];
__device__ float g_stat[4];
__device__ float g_colsum[F];

// bf16 split operands for tensor-core GEMM
__device__ __nv_bfloat16 g_A1b[N_NODES * F];
__device__ __nv_bfloat16 g_A2b[N_NODES * F];
// transposed + split weights: [wid][n*256+k], wid: 0=self1 1=nb1 2=self2 3=nb2
__device__ __nv_bfloat16 g_Wt1[4 * F * F];
__device__ __nv_bfloat16 g_Wt2[4 * F * F];

// CSR scratch
__device__ int   g_cnt[N_NODES];
__device__ int   g_rowptr[N_NODES + 1];
__device__ int   g_bsum[SCAN_NBLK];
__device__ int   g_boff[SCAN_NBLK];
__device__ int   g_csr_col[E_EDGES];
__device__ float g_csr_val[E_EDGES];

#define NEG_BIG (-3.0e38f)
#define SMEM_SWIZZLE_128B(o) ((o) ^ (((o) >> 3) & 0x70))

__device__ __forceinline__ uint32_t smem_u32(const void* p) {
    uint32_t a;
    asm("{ .reg .u64 t; cvta.to.shared.u64 t, %1; cvt.u32.u64 %0, t; }"
        : "=r"(a) : "l"(p));
    return a;
}

__device__ __forceinline__ void ldmatrix_x4(uint32_t* r, uint32_t addr) {
    asm volatile("ldmatrix.sync.aligned.m8n8.x4.shared.b16 {%0,%1,%2,%3}, [%4];"
        : "=r"(r[0]), "=r"(r[1]), "=r"(r[2]), "=r"(r[3]) : "r"(addr));
}

__device__ __forceinline__ void mma_bf16(float* d, const uint32_t* a, const uint32_t* b) {
    asm volatile(
        "mma.sync.aligned.m16n8k16.row.col.f32.bf16.bf16.f32 "
        "{%0,%1,%2,%3}, {%4,%5,%6,%7}, {%8,%9}, {%0,%1,%2,%3};"
        : "+f"(d[0]), "+f"(d[1]), "+f"(d[2]), "+f"(d[3])
        : "r"(a[0]), "r"(a[1]), "r"(a[2]), "r"(a[3]), "r"(b[0]), "r"(b[1]));
}

// ---------------- small utility kernels ----------------
__global__ void k_zero_colsum() {
    if (threadIdx.x < F) g_colsum[threadIdx.x] = 0.0f;
}

__global__ void k_zero_cnt() {
    int i = blockIdx.x * blockDim.x + threadIdx.x;
    if (i < N_NODES) g_cnt[i] = 0;
}

// ---------------- CSR build ------------------------------------------------
__global__ void k_hist(const int* __restrict__ er) {
    int i = blockIdx.x * blockDim.x + threadIdx.x;
    if (i < E_EDGES) atomicAdd(&g_cnt[er[i]], 1);
}

__device__ __forceinline__ int warp_scan_incl(int v, int lane) {
    #pragma unroll
    for (int off = 1; off < 32; off <<= 1) {
        int t = __shfl_up_sync(0xffffffffu, v, off);
        if (lane >= off) v += t;
    }
    return v;
}

__global__ void k_scan1() {
    __shared__ int wsum[8];
    int t = threadIdx.x;
    int lane = t & 31, wid = t >> 5;
    int i = blockIdx.x * SCAN_BLK + t;
    int v = (i < N_NODES) ? g_cnt[i] : 0;
    int incl = warp_scan_incl(v, lane);
    if (lane == 31) wsum[wid] = incl;
    __syncthreads();
    if (wid == 0) {
        int s = (lane < 8) ? wsum[lane] : 0;
        s = warp_scan_incl(s, lane);
        if (lane < 8) wsum[lane] = s;
    }
    __syncthreads();
    int off = wid ? wsum[wid - 1] : 0;
    incl += off;
    if (i < N_NODES) g_rowptr[i] = incl - v;
    if (t == SCAN_BLK - 1) g_bsum[blockIdx.x] = incl;
}

__global__ void k_scan2() {
    __shared__ int wsum[16];
    int t = threadIdx.x;
    int lane = t & 31, wid = t >> 5;
    int v = (t < SCAN_NBLK) ? g_bsum[t] : 0;
    int incl = warp_scan_incl(v, lane);
    if (lane == 31) wsum[wid] = incl;
    __syncthreads();
    if (wid == 0) {
        int s = (lane < 16) ? wsum[lane] : 0;
        s = warp_scan_incl(s, lane);
        if (lane < 16) wsum[lane] = s;
    }
    __syncthreads();
    int off = wid ? wsum[wid - 1] : 0;
    incl += off;
    if (t < SCAN_NBLK) g_boff[t] = incl - v;
}

__global__ void k_scan3() {
    int i = blockIdx.x * blockDim.x + threadIdx.x;
    if (i < N_NODES) {
        int val = g_rowptr[i] + g_boff[i >> 8];
        g_rowptr[i] = val;
        g_cnt[i] = val;
    }
    if (i == 0) g_rowptr[N_NODES] = E_EDGES;
}

__global__ void k_scatter(const int* __restrict__ er, const int* __restrict__ ec,
                          const float* __restrict__ ev) {
    int i = blockIdx.x * blockDim.x + threadIdx.x;
    if (i < E_EDGES) {
        int row = er[i];
        int pos = atomicAdd(&g_cnt[row], 1);
        g_csr_col[pos] = ec[i];
        g_csr_val[pos] = ev[i];
    }
}

// ---------------- bf16 split prep -----------------------------------------
__global__ void k_splitA(const float* __restrict__ src, const float* __restrict__ rvec)
{
    int i = blockIdx.x * blockDim.x + threadIdx.x;
    if (i >= N_NODES * F) return;
    float x = src[i];
    if (rvec) x *= rvec[i >> 8];
    __nv_bfloat16 h = __float2bfloat16(x);
    g_A1b[i] = h;
    g_A2b[i] = __float2bfloat16(x - __bfloat162float(h));
}

// weight transpose + split: out[n*256+k] from W[k*256+n]
__global__ void k_wsplit(const float* __restrict__ W, int wid4)
{
    int i = blockIdx.x * blockDim.x + threadIdx.x;
    if (i >= F * F) return;
    int n = i >> 8, k = i & 255;
    float x = W[k * F + n];
    __nv_bfloat16 h = __float2bfloat16(x);
    g_Wt1[wid4 * F * F + i] = h;
    g_Wt2[wid4 * F * F + i] = __float2bfloat16(x - __bfloat162float(h));
}

// ---------------- mma.sync dual GEMM --------------------------------------
// CTA: 128 M-rows x 64 N-cols, BOTH outputs (warps 0-3: self, 4-7: nb).
// A = A1 + A2 (bf16 split, device globals), W as transposed bf16 splits [n][k].
// 3 passes: (A1,W1), (A2,W1), (A1,W2); K=256 in steps of 64.
__global__ __launch_bounds__(256) void k_gemm_mma(
    const __nv_bfloat16* __restrict__ Ws1, const __nv_bfloat16* __restrict__ Ws2,
    const __nv_bfloat16* __restrict__ Wn1, const __nv_bfloat16* __restrict__ Wn2,
    const float* __restrict__ bias,
    float* __restrict__ Cs, float* __restrict__ Cn, int M)
{
    __shared__ __align__(16) char sA [128 * 128];   // 128 rows x 64 bf16 (swizzled)
    __shared__ __align__(16) char sBs[64 * 128];
    __shared__ __align__(16) char sBn[64 * 128];

    const int tid  = threadIdx.x;
    const int wid  = tid >> 5;
    const int lane = tid & 31;
    const int rowBlock = blockIdx.x * 128;
    const int nBlock   = blockIdx.y * 64;
    const int grp = wid >> 2;            // 0 = self, 1 = nb
    const int wm  = (wid & 3) * 32;      // warp m-offset

    const uint32_t sAu = smem_u32(sA);
    const uint32_t sBu = smem_u32(grp ? sBn : sBs);

    float acc[2][8][4];
    #pragma unroll
    for (int mi = 0; mi < 2; mi++)
        #pragma unroll
        for (int ni = 0; ni < 8; ni++)
            #pragma unroll
            for (int q = 0; q < 4; q++) acc[mi][ni][q] = 0.0f;

    // precomputed ldmatrix lane addresses (byte offsets before swizzle base)
    const int aRow = (lane & 15);
    const int aKc  = (lane >> 4) << 3;               // 0 or 8 (bf16 units)
    const int bN   = ((lane >> 4) & 1) * 8 + (lane & 7);
    const int bKc  = ((lane >> 3) & 1) * 8;

    #pragma unroll 1
    for (int pass = 0; pass < 3; pass++) {
        const __nv_bfloat16* Ap  = (pass == 1) ? g_A2b : g_A1b;
        const __nv_bfloat16* WsP = (pass == 2) ? Ws2 : Ws1;
        const __nv_bfloat16* WnP = (pass == 2) ? Wn2 : Wn1;

        #pragma unroll 1
        for (int k0 = 0; k0 < F; k0 += 64) {
            // ---- load A tile 128x64 ----
            #pragma unroll
            for (int it = 0; it < 4; it++) {
                int i = tid + it * 256;          // 0..1023
                int r = i >> 3, j = i & 7;
                uint32_t off = (uint32_t)(r * 128 + j * 16);
                uint4 v = make_uint4(0u, 0u, 0u, 0u);
                int grow = rowBlock + r;
                if (grow < M)
                    v = *reinterpret_cast<const uint4*>(Ap + (size_t)grow * F + k0 + j * 8);
                *reinterpret_cast<uint4*>(sA + SMEM_SWIZZLE_128B(off)) = v;
            }
            // ---- load B tiles 64x64 (self + nb) ----
            #pragma unroll
            for (int it = 0; it < 2; it++) {
                int i = tid + it * 256;          // 0..511
                int r = i >> 3, j = i & 7;
                uint32_t off = SMEM_SWIZZLE_128B((uint32_t)(r * 128 + j * 16));
                *reinterpret_cast<uint4*>(sBs + off) =
                    *reinterpret_cast<const uint4*>(WsP + (size_t)(nBlock + r) * F + k0 + j * 8);
                *reinterpret_cast<uint4*>(sBn + off) =
                    *reinterpret_cast<const uint4*>(WnP + (size_t)(nBlock + r) * F + k0 + j * 8);
            }
            __syncthreads();

            // ---- compute 64 k ----
            #pragma unroll
            for (int kk = 0; kk < 64; kk += 16) {
                uint32_t a[2][4];
                #pragma unroll
                for (int mi = 0; mi < 2; mi++) {
                    int row = wm + mi * 16 + aRow;
                    uint32_t addr = sAu +
                        SMEM_SWIZZLE_128B((uint32_t)(row * 128 + (kk + aKc) * 2));
                    ldmatrix_x4(a[mi], addr);
                }
                uint32_t b[8][2];
                #pragma unroll
                for (int np = 0; np < 4; np++) {
                    uint32_t r4[4];
                    int n = np * 16 + bN;
                    uint32_t addr = sBu +
                        SMEM_SWIZZLE_128B((uint32_t)(n * 128 + (kk + bKc) * 2));
                    ldmatrix_x4(r4, addr);
                    b[np * 2][0]     = r4[0];
                    b[np * 2][1]     = r4[1];
                    b[np * 2 + 1][0] = r4[2];
                    b[np * 2 + 1][1] = r4[3];
                }
                #pragma unroll
                for (int mi = 0; mi < 2; mi++)
                    #pragma unroll
                    for (int ni = 0; ni < 8; ni++)
                        mma_bf16(acc[mi][ni], a[mi], b[ni]);
            }
            __syncthreads();
        }
    }

    // ---- epilogue ----
    float* C = grp ? Cn : Cs;
    const int rq = lane >> 2;          // 0..7
    const int cq = (lane & 3) * 2;
    #pragma unroll
    for (int mi = 0; mi < 2; mi++) {
        #pragma unroll
        for (int ni = 0; ni < 8; ni++) {
            int n = nBlock + ni * 8 + cq;
            float b0 = 0.f, b1 = 0.f;
            if (grp == 0) { b0 = bias[n]; b1 = bias[n + 1]; }
            int m0 = rowBlock + wm + mi * 16 + rq;
            if (m0 < M) {
                float2 o = make_float2(acc[mi][ni][0] + b0, acc[mi][ni][1] + b1);
                *reinterpret_cast<float2*>(C + (size_t)m0 * F + n) = o;
            }
            int m1 = m0 + 8;
            if (m1 < M) {
                float2 o = make_float2(acc[mi][ni][2] + b0, acc[mi][ni][3] + b1);
                *reinterpret_cast<float2*>(C + (size_t)m1 * F + n) = o;
            }
        }
    }
}

// ---------------- CSR SpMM: one warp per row, register accumulators ----------
__device__ __forceinline__ void fma4(float4& a, float v, const float4& s) {
    a.x = fmaf(v, s.x, a.x);
    a.y = fmaf(v, s.y, a.y);
    a.z = fmaf(v, s.z, a.z);
    a.w = fmaf(v, s.w, a.w);
}

__global__ __launch_bounds__(256) void k_spmm_csr()
{
    int warp = (blockIdx.x * blockDim.x + threadIdx.x) >> 5;
    int lane = threadIdx.x & 31;
    if (warp >= N_NODES) return;
    int s = g_rowptr[warp];
    int e = g_rowptr[warp + 1];

    const float4* S4 = reinterpret_cast<const float4*>(g_S);
    float4 a0 = make_float4(0.f, 0.f, 0.f, 0.f);
    float4 a1 = make_float4(0.f, 0.f, 0.f, 0.f);

    int i = s;
    for (; i + 1 < e; i += 2) {
        int   c0 = g_csr_col[i];
        int   c1 = g_csr_col[i + 1];
        float v0 = g_csr_val[i];
        float v1 = g_csr_val[i + 1];
        const float4* p0 = S4 + (size_t)c0 * 64;
        const float4* p1 = S4 + (size_t)c1 * 64;
        float4 s00 = __ldg(p0 + lane);
        float4 s01 = __ldg(p0 + 32 + lane);
        float4 s10 = __ldg(p1 + lane);
        float4 s11 = __ldg(p1 + 32 + lane);
        fma4(a0, v0, s00); fma4(a1, v0, s01);
        fma4(a0, v1, s10); fma4(a1, v1, s11);
    }
    if (i < e) {
        int   c0 = g_csr_col[i];
        float v0 = g_csr_val[i];
        const float4* p0 = S4 + (size_t)c0 * 64;
        float4 s00 = __ldg(p0 + lane);
        float4 s01 = __ldg(p0 + 32 + lane);
        fma4(a0, v0, s00); fma4(a1, v0, s01);
    }

    float4* A4 = reinterpret_cast<float4*>(g_A) + (size_t)warp * 64;
    float4 d0 = A4[lane];
    float4 d1 = A4[lane + 32];
    d0.x += a0.x; d0.y += a0.y; d0.z += a0.z; d0.w += a0.w;
    d1.x += a1.x; d1.y += a1.y; d1.z += a1.z; d1.w += a1.w;
    A4[lane]      = d0;
    A4[lane + 32] = d1;
}

// ---------------- relu(A)->X1 and gate dot products -----------------------
__global__ void k_relu_gates(const float* __restrict__ w1, const float* __restrict__ b1g,
                             const float* __restrict__ w2, const float* __restrict__ b2g)
{
    int warp = (blockIdx.x * blockDim.x + threadIdx.x) >> 5;
    int lane = threadIdx.x & 31;
    if (warp >= N_NODES) return;
    const float4* A4 = reinterpret_cast<const float4*>(g_A) + (size_t)warp * 64;
    float4*       X4 = reinterpret_cast<float4*>(g_X1)      + (size_t)warp * 64;
    const float4* W1 = reinterpret_cast<const float4*>(w1);
    const float4* W2 = reinterpret_cast<const float4*>(w2);
    float d1 = 0.f, d2 = 0.f;
    #pragma unroll
    for (int j = 0; j < 2; j++) {
        int idx = lane + 32 * j;
        float4 a = A4[idx];
        a.x = fmaxf(a.x, 0.f); a.y = fmaxf(a.y, 0.f);
        a.z = fmaxf(a.z, 0.f); a.w = fmaxf(a.w, 0.f);
        X4[idx] = a;
        float4 u = W1[idx];
        float4 t = W2[idx];
        d1 += a.x * u.x + a.y * u.y + a.z * u.z + a.w * u.w;
        d2 += a.x * t.x + a.y * t.y + a.z * t.z + a.w * t.w;
    }
    #pragma unroll
    for (int off = 16; off; off >>= 1) {
        d1 += __shfl_xor_sync(0xffffffffu, d1, off);
        d2 += __shfl_xor_sync(0xffffffffu, d2, off);
    }
    if (lane == 0) {
        g_g1[warp] = d1 + b1g[0];
        g_g2[warp] = d2 + b2g[0];
    }
}

// ---------------- softmax over nodes: online (max, sumexp) -----------------
__device__ __forceinline__ void merge_ms(float& m, float& s, float mb, float sb) {
    float M = fmaxf(m, mb);
    s = s * __expf(m - M) + sb * __expf(mb - M);
    m = M;
}

__global__ void k_softmax_part()
{
    float m1 = NEG_BIG, s1 = 0.f, m2 = NEG_BIG, s2 = 0.f;
    for (int i = blockIdx.x * blockDim.x + threadIdx.x; i < N_NODES;
         i += gridDim.x * blockDim.x) {
        float v1 = g_g1[i];
        merge_ms(m1, s1, v1, 1.0f);
        float v2 = g_g2[i];
        merge_ms(m2, s2, v2, 1.0f);
    }
    __shared__ float sm1[256], ss1[256], sm2[256], ss2[256];
    int t = threadIdx.x;
    sm1[t] = m1; ss1[t] = s1; sm2[t] = m2; ss2[t] = s2;
    __syncthreads();
    for (int off = 128; off; off >>= 1) {
        if (t < off) {
            float mm = sm1[t], ss = ss1[t];
            merge_ms(mm, ss, sm1[t + off], ss1[t + off]);
            sm1[t] = mm; ss1[t] = ss;
            mm = sm2[t]; ss = ss2[t];
            merge_ms(mm, ss, sm2[t + off], ss2[t + off]);
            sm2[t] = mm; ss2[t] = ss;
        }
        __syncthreads();
    }
    if (t == 0) {
        g_part[blockIdx.x * 4 + 0] = sm1[0];
        g_part[blockIdx.x * 4 + 1] = ss1[0];
        g_part[blockIdx.x * 4 + 2] = sm2[0];
        g_part[blockIdx.x * 4 + 3] = ss2[0];
    }
}

__global__ void k_softmax_final(int nparts)
{
    __shared__ float sm1[128], ss1[128], sm2[128], ss2[128];
    int t = threadIdx.x;
    float m1 = NEG_BIG, s1 = 0.f, m2 = NEG_BIG, s2 = 0.f;
    if (t < nparts) {
        m1 = g_part[t * 4 + 0]; s1 = g_part[t * 4 + 1];
        m2 = g_part[t * 4 + 2]; s2 = g_part[t * 4 + 3];
    }
    sm1[t] = m1; ss1[t] = s1; sm2[t] = m2; ss2[t] = s2;
    __syncthreads();
    for (int off = 64; off; off >>= 1) {
        if (t < off) {
            float mm = sm1[t], ss = ss1[t];
            merge_ms(mm, ss, sm1[t + off], ss1[t + off]);
            sm1[t] = mm; ss1[t] = ss;
            mm = sm2[t]; ss = ss2[t];
            merge_ms(mm, ss, sm2[t + off], ss2[t + off]);
            sm2[t] = mm; ss2[t] = ss;
        }
        __syncthreads();
    }
    if (t == 0) {
        g_stat[0] = sm1[0]; g_stat[1] = ss1[0];
        g_stat[2] = sm2[0]; g_stat[3] = ss2[0];
    }
}

__global__ void k_rz()
{
    int i = blockIdx.x * blockDim.x + threadIdx.x;
    if (i < N_NODES) {
        g_r[i] = __expf(g_g1[i] - g_stat[0]) / g_stat[1];
        g_z[i] = __expf(g_g2[i] - g_stat[2]) / g_stat[3];
    }
}

// ---------------- final mix + column-sum --------------------------------
__global__ void k_mix(float* __restrict__ out)
{
    int f = threadIdx.x;
    float local = 0.f;
    for (int row = blockIdx.x; row < N_NODES; row += gridDim.x) {
        float z  = g_z[row];
        float a  = g_A [(size_t)row * F + f];
        float x1 = g_X1[(size_t)row * F + f];
        float xe = (1.f - z) * x1 + z * fmaxf(a, 0.f);
        out[(size_t)row * F + f] = xe;
        local += xe;
    }
    atomicAdd(&g_colsum[f], local);
}

__global__ void k_out(const float* __restrict__ e2pw, const float* __restrict__ e2pb,
                      float* __restrict__ out)
{
    __shared__ float mean[F];
    for (int i = threadIdx.x; i < F; i += blockDim.x)
        mean[i] = g_colsum[i] * (1.0f / N_NODES);
    __syncthreads();
    int j = threadIdx.x;
    if (j < NOUT) {
        float acc = e2pb[j];
        #pragma unroll 8
        for (int k = 0; k < F; k++)
            acc += mean[k] * e2pw[(size_t)k * NOUT + j];
        out[(size_t)N_NODES * F + j] = acc;
    }
}

// ---------------- launch ----------------
extern "C" void kernel_launch(void* const* d_in, const int* in_sizes, int n_in,
                              void* d_out, int out_size)
{
    const float* inputs  = (const float*)d_in[0];
    const int*   er      = (const int*)  d_in[1];
    const int*   ec      = (const int*)  d_in[2];
    const float* ev      = (const float*)d_in[3];
    const float* W_self1 = (const float*)d_in[4];
    const float* W_nb1   = (const float*)d_in[5];
    const float* b1      = (const float*)d_in[6];
    const float* W_self2 = (const float*)d_in[7];
    const float* W_nb2   = (const float*)d_in[8];
    const float* b2      = (const float*)d_in[9];
    const float* g1w     = (const float*)d_in[10];
    const float* g1b     = (const float*)d_in[11];
    const float* g2w     = (const float*)d_in[12];
    const float* g2b     = (const float*)d_in[13];
    const float* e2pw    = (const float*)d_in[14];
    const float* e2pb    = (const float*)d_in[15];
    float* out = (float*)d_out;

    float *pA, *pS, *pX1, *pR;
    cudaGetSymbolAddress((void**)&pA,  g_A);
    cudaGetSymbolAddress((void**)&pS,  g_S);
    cudaGetSymbolAddress((void**)&pX1, g_X1);
    cudaGetSymbolAddress((void**)&pR,  g_r);
    __nv_bfloat16 *pWt1, *pWt2;
    cudaGetSymbolAddress((void**)&pWt1, g_Wt1);
    cudaGetSymbolAddress((void**)&pWt2, g_Wt2);

    const int EB = (E_EDGES + 255) / 256;
    const int NB = (N_NODES + 255) / 256;
    const int SB = (N_NODES * F + 255) / 256;
    dim3 gmm((N_NODES + 127) / 128, 4);    // (782, 4): 64 N-cols per y

    k_zero_colsum<<<1, 256>>>();

    // ---- CSR build (shared by both SpMMs) ----
    k_zero_cnt<<<NB, 256>>>();
    k_hist<<<EB, 256>>>(er);
    k_scan1<<<SCAN_NBLK, SCAN_BLK>>>();
    k_scan2<<<1, 512>>>();
    k_scan3<<<NB, 256>>>();
    k_scatter<<<EB, 256>>>(er, ec, ev);

    // ---- weight transpose + bf16 split ----
    k_wsplit<<<(F * F + 255) / 256, 256>>>(W_self1, 0);
    k_wsplit<<<(F * F + 255) / 256, 256>>>(W_nb1,   1);
    k_wsplit<<<(F * F + 255) / 256, 256>>>(W_self2, 2);
    k_wsplit<<<(F * F + 255) / 256, 256>>>(W_nb2,   3);

    // ---- layer 1: split inputs, dual tensor-core GEMM ----
    k_splitA<<<SB, 256>>>(inputs, nullptr);
    k_gemm_mma<<<gmm, 256>>>(pWt1 + 0 * F * F, pWt2 + 0 * F * F,
                             pWt1 + 1 * F * F, pWt2 + 1 * F * F,
                             b1, pA, pS, N_NODES);
    k_spmm_csr<<<(N_NODES * 32 + 255) / 256, 256>>>();
    k_relu_gates<<<N_NODES / 8, 256>>>(g1w, g1b, g2w, g2b);

    // ---- softmax gates over nodes ----
    k_softmax_part<<<120, 256>>>();
    k_softmax_final<<<1, 128>>>(120);
    k_rz<<<NB, 256>>>();

    // ---- layer 2: split X1*r, dual tensor-core GEMM ----
    k_splitA<<<SB, 256>>>(pX1, pR);
    k_gemm_mma<<<gmm, 256>>>(pWt1 + 2 * F * F, pWt2 + 2 * F * F,
                             pWt1 + 3 * F * F, pWt2 + 3 * F * F,
                             b2, pA, pS, N_NODES);
    k_spmm_csr<<<(N_NODES * 32 + 255) / 256, 256>>>();

    // ---- mix, mean, head ----
    k_mix<<<512, 256>>>(out);
    k_out<<<1, 128>>>(e2pw, e2pb, out);
}

// round 7
// speedup vs baseline: 3.1905x; 1.4879x over previous
#include <cuda_runtime.h>
#include <cuda_bf16.h>
#include <cuda_fp16.h>
#include <math.h>
#include <stdint.h>

#define N_NODES 100000
#define E_EDGES 3200000
#define F 256
#define NOUT 128

#define SCAN_BLK 256
#define SCAN_NBLK ((N_NODES + SCAN_BLK - 1) / SCAN_BLK)   // 391

// ---------------- scratch (device globals; no allocation allowed) ----------
__device__ __half g_Sh[N_NODES * F]; // support = x @ W_nb (fp16 for cheap gather)
__device__ float g_A [N_NODES * F];  // accumulator: x@W_self + b, then += spmm
__device__ float g_X1[N_NODES * F];  // x after layer-1 relu
__device__ float g_g1[N_NODES];
__device__ float g_g2[N_NODES];
__device__ float g_r [N_NODES];
__device__ float g_z [N_NODES];
__device__ float g_part[512 * 4];
__device__ float g_stat[4];
__device__ float g_colsum[F];

// transposed + split weights: [wid][n*256+k], wid: 0=self1 1=nb1 2=self2 3=nb2
__device__ __nv_bfloat16 g_Wt1[4 * F * F];
__device__ __nv_bfloat16 g_Wt2[4 * F * F];

// CSR scratch
__device__ int   g_cnt[N_NODES];
__device__ int   g_rowptr[N_NODES + 1];
__device__ int   g_bsum[SCAN_NBLK];
__device__ int   g_boff[SCAN_NBLK];
__device__ int   g_csr_col[E_EDGES];
__device__ float g_csr_val[E_EDGES];

#define NEG_BIG (-3.0e38f)
#define SMEM_SWIZZLE_128B(o) ((o) ^ (((o) >> 3) & 0x70))

__device__ __forceinline__ uint32_t smem_u32(const void* p) {
    uint32_t a;
    asm("{ .reg .u64 t; cvta.to.shared.u64 t, %1; cvt.u32.u64 %0, t; }"
        : "=r"(a) : "l"(p));
    return a;
}

__device__ __forceinline__ void ldmatrix_x4(uint32_t* r, uint32_t addr) {
    asm volatile("ldmatrix.sync.aligned.m8n8.x4.shared.b16 {%0,%1,%2,%3}, [%4];"
        : "=r"(r[0]), "=r"(r[1]), "=r"(r[2]), "=r"(r[3]) : "r"(addr));
}

__device__ __forceinline__ void mma_bf16(float* d, const uint32_t* a, const uint32_t* b) {
    asm volatile(
        "mma.sync.aligned.m16n8k16.row.col.f32.bf16.bf16.f32 "
        "{%0,%1,%2,%3}, {%4,%5,%6,%7}, {%8,%9}, {%0,%1,%2,%3};"
        : "+f"(d[0]), "+f"(d[1]), "+f"(d[2]), "+f"(d[3])
        : "r"(a[0]), "r"(a[1]), "r"(a[2]), "r"(a[3]), "r"(b[0]), "r"(b[1]));
}

// ---------------- small utility kernels ----------------
__global__ void k_zero_colsum() {
    if (threadIdx.x < F) g_colsum[threadIdx.x] = 0.0f;
}

__global__ void k_zero_cnt() {
    int i = blockIdx.x * blockDim.x + threadIdx.x;
    if (i < N_NODES) g_cnt[i] = 0;
}

// ---------------- CSR build ------------------------------------------------
__global__ void k_hist(const int* __restrict__ er) {
    int i = blockIdx.x * blockDim.x + threadIdx.x;
    if (i < E_EDGES) atomicAdd(&g_cnt[er[i]], 1);
}

__device__ __forceinline__ int warp_scan_incl(int v, int lane) {
    #pragma unroll
    for (int off = 1; off < 32; off <<= 1) {
        int t = __shfl_up_sync(0xffffffffu, v, off);
        if (lane >= off) v += t;
    }
    return v;
}

__global__ void k_scan1() {
    __shared__ int wsum[8];
    int t = threadIdx.x;
    int lane = t & 31, wid = t >> 5;
    int i = blockIdx.x * SCAN_BLK + t;
    int v = (i < N_NODES) ? g_cnt[i] : 0;
    int incl = warp_scan_incl(v, lane);
    if (lane == 31) wsum[wid] = incl;
    __syncthreads();
    if (wid == 0) {
        int s = (lane < 8) ? wsum[lane] : 0;
        s = warp_scan_incl(s, lane);
        if (lane < 8) wsum[lane] = s;
    }
    __syncthreads();
    int off = wid ? wsum[wid - 1] : 0;
    incl += off;
    if (i < N_NODES) g_rowptr[i] = incl - v;
    if (t == SCAN_BLK - 1) g_bsum[blockIdx.x] = incl;
}

__global__ void k_scan2() {
    __shared__ int wsum[16];
    int t = threadIdx.x;
    int lane = t & 31, wid = t >> 5;
    int v = (t < SCAN_NBLK) ? g_bsum[t] : 0;
    int incl = warp_scan_incl(v, lane);
    if (lane == 31) wsum[wid] = incl;
    __syncthreads();
    if (wid == 0) {
        int s = (lane < 16) ? wsum[lane] : 0;
        s = warp_scan_incl(s, lane);
        if (lane < 16) wsum[lane] = s;
    }
    __syncthreads();
    int off = wid ? wsum[wid - 1] : 0;
    incl += off;
    if (t < SCAN_NBLK) g_boff[t] = incl - v;
}

__global__ void k_scan3() {
    int i = blockIdx.x * blockDim.x + threadIdx.x;
    if (i < N_NODES) {
        int val = g_rowptr[i] + g_boff[i >> 8];
        g_rowptr[i] = val;
        g_cnt[i] = val;
    }
    if (i == 0) g_rowptr[N_NODES] = E_EDGES;
}

__global__ void k_scatter(const int* __restrict__ er, const int* __restrict__ ec,
                          const float* __restrict__ ev) {
    int i = blockIdx.x * blockDim.x + threadIdx.x;
    if (i < E_EDGES) {
        int row = er[i];
        int pos = atomicAdd(&g_cnt[row], 1);
        g_csr_col[pos] = ec[i];
        g_csr_val[pos] = ev[i];
    }
}

// ---------------- weight transpose + bf16 split ---------------------------
__global__ void k_wsplit(const float* __restrict__ W, int wid4)
{
    int i = blockIdx.x * blockDim.x + threadIdx.x;
    if (i >= F * F) return;
    int n = i >> 8, k = i & 255;
    float x = W[k * F + n];
    __nv_bfloat16 h = __float2bfloat16(x);
    g_Wt1[wid4 * F * F + i] = h;
    g_Wt2[wid4 * F * F + i] = __float2bfloat16(x - __bfloat162float(h));
}

// ---------------- fused-split mma.sync dual GEMM ---------------------------
// CTA: 128 M x 64 N for BOTH outputs (warps 0-3: self fp32+bias, 4-7: nb fp16).
// Loads fp32 A tile once per k-step, splits to bf16 hi/lo in smem, runs the
// 3 split-combos (A1B1, A2B1, A1B2) against the resident tile.
// smem layout (dynamic, 64 KB):
//   [0,16K)   A1   [16K,32K) A2
//   [32K,40K) Bs1  [40K,48K) Bn1  [48K,56K) Bs2  [56K,64K) Bn2
__global__ __launch_bounds__(256, 2) void k_gemm_fused(
    const float* __restrict__ Asrc, const float* __restrict__ rvec,
    const __nv_bfloat16* __restrict__ Ws1, const __nv_bfloat16* __restrict__ Ws2,
    const __nv_bfloat16* __restrict__ Wn1, const __nv_bfloat16* __restrict__ Wn2,
    const float* __restrict__ bias,
    float* __restrict__ Cs, __half* __restrict__ Sn, int M)
{
    extern __shared__ __align__(16) char smem[];

    const int tid  = threadIdx.x;
    const int wid  = tid >> 5;
    const int lane = tid & 31;
    const int rowBlock = blockIdx.x * 128;
    const int nBlock   = blockIdx.y * 64;
    const int grp = wid >> 2;            // 0 = self, 1 = nb
    const int wm  = (wid & 3) * 32;      // warp m-offset

    const uint32_t sA1u = smem_u32(smem);
    const uint32_t sA2u = sA1u + 16384;
    const uint32_t B1u  = sA1u + 32768 + (grp ? 8192 : 0);
    const uint32_t B2u  = sA1u + 49152 + (grp ? 8192 : 0);

    float acc[2][8][4];
    #pragma unroll
    for (int mi = 0; mi < 2; mi++)
        #pragma unroll
        for (int ni = 0; ni < 8; ni++)
            #pragma unroll
            for (int q = 0; q < 4; q++) acc[mi][ni][q] = 0.0f;

    const int aRow = (lane & 15);
    const int aKc  = (lane >> 4) << 3;
    const int bN   = ((lane >> 4) & 1) * 8 + (lane & 7);
    const int bKc  = ((lane >> 3) & 1) * 8;

    #pragma unroll 1
    for (int k0 = 0; k0 < F; k0 += 64) {
        // ---- load fp32 A tile 128x64, split to bf16 hi/lo in smem ----
        #pragma unroll
        for (int it = 0; it < 8; it++) {
            int idx = tid + it * 256;        // 0..2047 float4 slots
            int r   = idx >> 4;              // row 0..127
            int c4  = idx & 15;              // float4 within row
            int grow = rowBlock + r;
            float4 v = make_float4(0.f, 0.f, 0.f, 0.f);
            if (grow < M) {
                v = *reinterpret_cast<const float4*>(Asrc + (size_t)grow * F + k0 + c4 * 4);
                if (rvec) {
                    float rr = rvec[grow];
                    v.x *= rr; v.y *= rr; v.z *= rr; v.w *= rr;
                }
            }
            __nv_bfloat162 h01 = __floats2bfloat162_rn(v.x, v.y);
            __nv_bfloat162 h23 = __floats2bfloat162_rn(v.z, v.w);
            float2 f01 = __bfloat1622float2(h01);
            float2 f23 = __bfloat1622float2(h23);
            __nv_bfloat162 l01 = __floats2bfloat162_rn(v.x - f01.x, v.y - f01.y);
            __nv_bfloat162 l23 = __floats2bfloat162_rn(v.z - f23.x, v.w - f23.y);
            uint32_t off = SMEM_SWIZZLE_128B((uint32_t)(r * 128 + c4 * 8));
            uint2 hi, lo;
            hi.x = *reinterpret_cast<uint32_t*>(&h01);
            hi.y = *reinterpret_cast<uint32_t*>(&h23);
            lo.x = *reinterpret_cast<uint32_t*>(&l01);
            lo.y = *reinterpret_cast<uint32_t*>(&l23);
            *reinterpret_cast<uint2*>(smem + off)         = hi;
            *reinterpret_cast<uint2*>(smem + 16384 + off) = lo;
        }
        // ---- load 4 B tiles 64x64 bf16 ----
        #pragma unroll
        for (int t = 0; t < 4; t++) {
            const __nv_bfloat16* Wp = (t == 0) ? Ws1 : (t == 1) ? Wn1 : (t == 2) ? Ws2 : Wn2;
            char* dst = smem + 32768 + t * 8192;
            #pragma unroll
            for (int it = 0; it < 2; it++) {
                int idx = tid + it * 256;    // 0..511
                int r = idx >> 3, c = idx & 7;
                uint32_t off = SMEM_SWIZZLE_128B((uint32_t)(r * 128 + c * 16));
                *reinterpret_cast<uint4*>(dst + off) =
                    *reinterpret_cast<const uint4*>(Wp + (size_t)(nBlock + r) * F + k0 + c * 8);
            }
        }
        __syncthreads();

        // ---- 3 combos: (A1,B1), (A2,B1), (A1,B2) ----
        #pragma unroll 1
        for (int combo = 0; combo < 3; combo++) {
            const uint32_t Au = (combo == 1) ? sA2u : sA1u;
            const uint32_t Bu = (combo == 2) ? B2u  : B1u;
            #pragma unroll
            for (int kk = 0; kk < 64; kk += 16) {
                uint32_t a[2][4];
                #pragma unroll
                for (int mi = 0; mi < 2; mi++) {
                    int row = wm + mi * 16 + aRow;
                    ldmatrix_x4(a[mi], Au +
                        SMEM_SWIZZLE_128B((uint32_t)(row * 128 + (kk + aKc) * 2)));
                }
                uint32_t b[8][2];
                #pragma unroll
                for (int np = 0; np < 4; np++) {
                    uint32_t r4[4];
                    int n = np * 16 + bN;
                    ldmatrix_x4(r4, Bu +
                        SMEM_SWIZZLE_128B((uint32_t)(n * 128 + (kk + bKc) * 2)));
                    b[np * 2][0]     = r4[0];
                    b[np * 2][1]     = r4[1];
                    b[np * 2 + 1][0] = r4[2];
                    b[np * 2 + 1][1] = r4[3];
                }
                #pragma unroll
                for (int mi = 0; mi < 2; mi++)
                    #pragma unroll
                    for (int ni = 0; ni < 8; ni++)
                        mma_bf16(acc[mi][ni], a[mi], b[ni]);
            }
        }
        __syncthreads();
    }

    // ---- epilogue ----
    const int rq = lane >> 2;
    const int cq = (lane & 3) * 2;
    if (grp == 0) {
        #pragma unroll
        for (int mi = 0; mi < 2; mi++) {
            #pragma unroll
            for (int ni = 0; ni < 8; ni++) {
                int n = nBlock + ni * 8 + cq;
                float b0 = bias[n], b1 = bias[n + 1];
                int m0 = rowBlock + wm + mi * 16 + rq;
                if (m0 < M)
                    *reinterpret_cast<float2*>(Cs + (size_t)m0 * F + n) =
                        make_float2(acc[mi][ni][0] + b0, acc[mi][ni][1] + b1);
                int m1 = m0 + 8;
                if (m1 < M)
                    *reinterpret_cast<float2*>(Cs + (size_t)m1 * F + n) =
                        make_float2(acc[mi][ni][2] + b0, acc[mi][ni][3] + b1);
            }
        }
    } else {
        #pragma unroll
        for (int mi = 0; mi < 2; mi++) {
            #pragma unroll
            for (int ni = 0; ni < 8; ni++) {
                int n = nBlock + ni * 8 + cq;
                int m0 = rowBlock + wm + mi * 16 + rq;
                if (m0 < M)
                    *reinterpret_cast<__half2*>(Sn + (size_t)m0 * F + n) =
                        __floats2half2_rn(acc[mi][ni][0], acc[mi][ni][1]);
                int m1 = m0 + 8;
                if (m1 < M)
                    *reinterpret_cast<__half2*>(Sn + (size_t)m1 * F + n) =
                        __floats2half2_rn(acc[mi][ni][2], acc[mi][ni][3]);
            }
        }
    }
}

// ---------------- CSR SpMM: warp/row, fp16 gather, fp32 accum --------------
__global__ __launch_bounds__(256) void k_spmm_csr()
{
    int warp = (blockIdx.x * blockDim.x + threadIdx.x) >> 5;
    int lane = threadIdx.x & 31;
    if (warp >= N_NODES) return;
    int s = g_rowptr[warp];
    int e = g_rowptr[warp + 1];

    const uint4* Sv = reinterpret_cast<const uint4*>(g_Sh);  // 16B = 8 halfs
    float acc[8];
    #pragma unroll
    for (int j = 0; j < 8; j++) acc[j] = 0.f;

    int i = s;
    for (; i + 1 < e; i += 2) {
        int   c0 = g_csr_col[i];
        int   c1 = g_csr_col[i + 1];
        float v0 = g_csr_val[i];
        float v1 = g_csr_val[i + 1];
        uint4 q0 = __ldg(Sv + (size_t)c0 * 32 + lane);
        uint4 q1 = __ldg(Sv + (size_t)c1 * 32 + lane);
        const __half2* h0 = reinterpret_cast<const __half2*>(&q0);
        const __half2* h1 = reinterpret_cast<const __half2*>(&q1);
        #pragma unroll
        for (int j = 0; j < 4; j++) {
            float2 f0 = __half22float2(h0[j]);
            float2 f1 = __half22float2(h1[j]);
            acc[2 * j]     += v0 * f0.x + v1 * f1.x;
            acc[2 * j + 1] += v0 * f0.y + v1 * f1.y;
        }
    }
    if (i < e) {
        int   c0 = g_csr_col[i];
        float v0 = g_csr_val[i];
        uint4 q0 = __ldg(Sv + (size_t)c0 * 32 + lane);
        const __half2* h0 = reinterpret_cast<const __half2*>(&q0);
        #pragma unroll
        for (int j = 0; j < 4; j++) {
            float2 f0 = __half22float2(h0[j]);
            acc[2 * j]     += v0 * f0.x;
            acc[2 * j + 1] += v0 * f0.y;
        }
    }

    float* Ap = g_A + (size_t)warp * F + lane * 8;
    float4 d0 = *reinterpret_cast<float4*>(Ap);
    float4 d1 = *reinterpret_cast<float4*>(Ap + 4);
    d0.x += acc[0]; d0.y += acc[1]; d0.z += acc[2]; d0.w += acc[3];
    d1.x += acc[4]; d1.y += acc[5]; d1.z += acc[6]; d1.w += acc[7];
    *reinterpret_cast<float4*>(Ap)     = d0;
    *reinterpret_cast<float4*>(Ap + 4) = d1;
}

// ---------------- relu(A)->X1 and gate dot products -----------------------
__global__ void k_relu_gates(const float* __restrict__ w1, const float* __restrict__ b1g,
                             const float* __restrict__ w2, const float* __restrict__ b2g)
{
    int warp = (blockIdx.x * blockDim.x + threadIdx.x) >> 5;
    int lane = threadIdx.x & 31;
    if (warp >= N_NODES) return;
    const float4* A4 = reinterpret_cast<const float4*>(g_A) + (size_t)warp * 64;
    float4*       X4 = reinterpret_cast<float4*>(g_X1)      + (size_t)warp * 64;
    const float4* W1 = reinterpret_cast<const float4*>(w1);
    const float4* W2 = reinterpret_cast<const float4*>(w2);
    float d1 = 0.f, d2 = 0.f;
    #pragma unroll
    for (int j = 0; j < 2; j++) {
        int idx = lane + 32 * j;
        float4 a = A4[idx];
        a.x = fmaxf(a.x, 0.f); a.y = fmaxf(a.y, 0.f);
        a.z = fmaxf(a.z, 0.f); a.w = fmaxf(a.w, 0.f);
        X4[idx] = a;
        float4 u = W1[idx];
        float4 t = W2[idx];
        d1 += a.x * u.x + a.y * u.y + a.z * u.z + a.w * u.w;
        d2 += a.x * t.x + a.y * t.y + a.z * t.z + a.w * t.w;
    }
    #pragma unroll
    for (int off = 16; off; off >>= 1) {
        d1 += __shfl_xor_sync(0xffffffffu, d1, off);
        d2 += __shfl_xor_sync(0xffffffffu, d2, off);
    }
    if (lane == 0) {
        g_g1[warp] = d1 + b1g[0];
        g_g2[warp] = d2 + b2g[0];
    }
}

// ---------------- softmax over nodes: online (max, sumexp) -----------------
__device__ __forceinline__ void merge_ms(float& m, float& s, float mb, float sb) {
    float M = fmaxf(m, mb);
    s = s * __expf(m - M) + sb * __expf(mb - M);
    m = M;
}

__global__ void k_softmax_part()
{
    float m1 = NEG_BIG, s1 = 0.f, m2 = NEG_BIG, s2 = 0.f;
    for (int i = blockIdx.x * blockDim.x + threadIdx.x; i < N_NODES;
         i += gridDim.x * blockDim.x) {
        float v1 = g_g1[i];
        merge_ms(m1, s1, v1, 1.0f);
        float v2 = g_g2[i];
        merge_ms(m2, s2, v2, 1.0f);
    }
    __shared__ float sm1[256], ss1[256], sm2[256], ss2[256];
    int t = threadIdx.x;
    sm1[t] = m1; ss1[t] = s1; sm2[t] = m2; ss2[t] = s2;
    __syncthreads();
    for (int off = 128; off; off >>= 1) {
        if (t < off) {
            float mm = sm1[t], ss = ss1[t];
            merge_ms(mm, ss, sm1[t + off], ss1[t + off]);
            sm1[t] = mm; ss1[t] = ss;
            mm = sm2[t]; ss = ss2[t];
            merge_ms(mm, ss, sm2[t + off], ss2[t + off]);
            sm2[t] = mm; ss2[t] = ss;
        }
        __syncthreads();
    }
    if (t == 0) {
        g_part[blockIdx.x * 4 + 0] = sm1[0];
        g_part[blockIdx.x * 4 + 1] = ss1[0];
        g_part[blockIdx.x * 4 + 2] = sm2[0];
        g_part[blockIdx.x * 4 + 3] = ss2[0];
    }
}

__global__ void k_softmax_final(int nparts)
{
    __shared__ float sm1[128], ss1[128], sm2[128], ss2[128];
    int t = threadIdx.x;
    float m1 = NEG_BIG, s1 = 0.f, m2 = NEG_BIG, s2 = 0.f;
    if (t < nparts) {
        m1 = g_part[t * 4 + 0]; s1 = g_part[t * 4 + 1];
        m2 = g_part[t * 4 + 2]; s2 = g_part[t * 4 + 3];
    }
    sm1[t] = m1; ss1[t] = s1; sm2[t] = m2; ss2[t] = s2;
    __syncthreads();
    for (int off = 64; off; off >>= 1) {
        if (t < off) {
            float mm = sm1[t], ss = ss1[t];
            merge_ms(mm, ss, sm1[t + off], ss1[t + off]);
            sm1[t] = mm; ss1[t] = ss;
            mm = sm2[t]; ss = ss2[t];
            merge_ms(mm, ss, sm2[t + off], ss2[t + off]);
            sm2[t] = mm; ss2[t] = ss;
        }
        __syncthreads();
    }
    if (t == 0) {
        g_stat[0] = sm1[0]; g_stat[1] = ss1[0];
        g_stat[2] = sm2[0]; g_stat[3] = ss2[0];
    }
}

__global__ void k_rz()
{
    int i = blockIdx.x * blockDim.x + threadIdx.x;
    if (i < N_NODES) {
        g_r[i] = __expf(g_g1[i] - g_stat[0]) / g_stat[1];
        g_z[i] = __expf(g_g2[i] - g_stat[2]) / g_stat[3];
    }
}

// ---------------- final mix + column-sum --------------------------------
__global__ void k_mix(float* __restrict__ out)
{
    int f = threadIdx.x;
    float local = 0.f;
    for (int row = blockIdx.x; row < N_NODES; row += gridDim.x) {
        float z  = g_z[row];
        float a  = g_A [(size_t)row * F + f];
        float x1 = g_X1[(size_t)row * F + f];
        float xe = (1.f - z) * x1 + z * fmaxf(a, 0.f);
        out[(size_t)row * F + f] = xe;
        local += xe;
    }
    atomicAdd(&g_colsum[f], local);
}

__global__ void k_out(const float* __restrict__ e2pw, const float* __restrict__ e2pb,
                      float* __restrict__ out)
{
    __shared__ float mean[F];
    for (int i = threadIdx.x; i < F; i += blockDim.x)
        mean[i] = g_colsum[i] * (1.0f / N_NODES);
    __syncthreads();
    int j = threadIdx.x;
    if (j < NOUT) {
        float acc = e2pb[j];
        #pragma unroll 8
        for (int k = 0; k < F; k++)
            acc += mean[k] * e2pw[(size_t)k * NOUT + j];
        out[(size_t)N_NODES * F + j] = acc;
    }
}

// ---------------- launch ----------------
extern "C" void kernel_launch(void* const* d_in, const int* in_sizes, int n_in,
                              void* d_out, int out_size)
{
    const float* inputs  = (const float*)d_in[0];
    const int*   er      = (const int*)  d_in[1];
    const int*   ec      = (const int*)  d_in[2];
    const float* ev      = (const float*)d_in[3];
    const float* W_self1 = (const float*)d_in[4];
    const float* W_nb1   = (const float*)d_in[5];
    const float* b1      = (const float*)d_in[6];
    const float* W_self2 = (const float*)d_in[7];
    const float* W_nb2   = (const float*)d_in[8];
    const float* b2      = (const float*)d_in[9];
    const float* g1w     = (const float*)d_in[10];
    const float* g1b     = (const float*)d_in[11];
    const float* g2w     = (const float*)d_in[12];
    const float* g2b     = (const float*)d_in[13];
    const float* e2pw    = (const float*)d_in[14];
    const float* e2pb    = (const float*)d_in[15];
    float* out = (float*)d_out;

    float *pA, *pX1, *pR;
    __half* pSh;
    cudaGetSymbolAddress((void**)&pA,  g_A);
    cudaGetSymbolAddress((void**)&pX1, g_X1);
    cudaGetSymbolAddress((void**)&pR,  g_r);
    cudaGetSymbolAddress((void**)&pSh, g_Sh);
    __nv_bfloat16 *pWt1, *pWt2;
    cudaGetSymbolAddress((void**)&pWt1, g_Wt1);
    cudaGetSymbolAddress((void**)&pWt2, g_Wt2);

    const int SMEM_GEMM = 65536;
    cudaFuncSetAttribute(k_gemm_fused, cudaFuncAttributeMaxDynamicSharedMemorySize, SMEM_GEMM);

    const int EB = (E_EDGES + 255) / 256;
    const int NB = (N_NODES + 255) / 256;
    dim3 gmm((N_NODES + 127) / 128, 4);    // (782, 4): 64 N-cols per y

    k_zero_colsum<<<1, 256>>>();

    // ---- CSR build (shared by both SpMMs) ----
    k_zero_cnt<<<NB, 256>>>();
    k_hist<<<EB, 256>>>(er);
    k_scan1<<<SCAN_NBLK, SCAN_BLK>>>();
    k_scan2<<<1, 512>>>();
    k_scan3<<<NB, 256>>>();
    k_scatter<<<EB, 256>>>(er, ec, ev);

    // ---- weight transpose + bf16 split ----
    k_wsplit<<<(F * F + 255) / 256, 256>>>(W_self1, 0);
    k_wsplit<<<(F * F + 255) / 256, 256>>>(W_nb1,   1);
    k_wsplit<<<(F * F + 255) / 256, 256>>>(W_self2, 2);
    k_wsplit<<<(F * F + 255) / 256, 256>>>(W_nb2,   3);

    // ---- layer 1: fused-split dual tensor-core GEMM ----
    k_gemm_fused<<<gmm, 256, SMEM_GEMM>>>(inputs, nullptr,
                             pWt1 + 0 * F * F, pWt2 + 0 * F * F,
                             pWt1 + 1 * F * F, pWt2 + 1 * F * F,
                             b1, pA, pSh, N_NODES);
    k_spmm_csr<<<(N_NODES * 32 + 255) / 256, 256>>>();
    k_relu_gates<<<N_NODES / 8, 256>>>(g1w, g1b, g2w, g2b);

    // ---- softmax gates over nodes ----
    k_softmax_part<<<120, 256>>>();
    k_softmax_final<<<1, 128>>>(120);
    k_rz<<<NB, 256>>>();

    // ---- layer 2: fused-split dual tensor-core GEMM (rows scaled by r) ----
    k_gemm_fused<<<gmm, 256, SMEM_GEMM>>>(pX1, pR,
                             pWt1 + 2 * F * F, pWt2 + 2 * F * F,
                             pWt1 + 3 * F * F, pWt2 + 3 * F * F,
                             b2, pA, pSh, N_NODES);
    k_spmm_csr<<<(N_NODES * 32 + 255) / 256, 256>>>();

    // ---- mix, mean, head ----
    k_mix<<<512, 256>>>(out);
    k_out<<<1, 128>>>(e2pw, e2pb, out);
}

// round 8
// speedup vs baseline: 3.5240x; 1.1045x over previous
#include <cuda_runtime.h>
#include <cuda_bf16.h>
#include <cuda_fp16.h>
#include <math.h>
#include <stdint.h>

#define N_NODES 100000
#define E_EDGES 3200000
#define F 256
#define NOUT 128

#define SCAN_BLK 256
#define SCAN_NBLK ((N_NODES + SCAN_BLK - 1) / SCAN_BLK)   // 391

// ---------------- scratch (device globals; no allocation allowed) ----------
__device__ __half g_Sh[N_NODES * F]; // support = x @ W_nb (fp16 for cheap gather)
__device__ float g_A [N_NODES * F];  // x@W_self + b (GEMM output, SpMM base)
__device__ float g_X1[N_NODES * F];  // x after layer-1 relu
__device__ float g_g1[N_NODES];
__device__ float g_g2[N_NODES];
__device__ float g_r [N_NODES];
__device__ float g_z [N_NODES];
__device__ float g_part[512 * 4];
__device__ float g_stat[4];
__device__ float g_colsum[F];

// transposed + split weights: [wid][n*256+k], wid: 0=self1 1=nb1 2=self2 3=nb2
__device__ __nv_bfloat16 g_Wt1[4 * F * F];
__device__ __nv_bfloat16 g_Wt2[4 * F * F];

// CSR scratch
__device__ int   g_cnt[N_NODES];
__device__ int   g_rowptr[N_NODES + 1];
__device__ int   g_bsum[SCAN_NBLK];
__device__ int   g_boff[SCAN_NBLK];
__device__ int   g_csr_col[E_EDGES];
__device__ float g_csr_val[E_EDGES];

#define NEG_BIG (-3.0e38f)
#define SMEM_SWIZZLE_128B(o) ((o) ^ (((o) >> 3) & 0x70))

__device__ __forceinline__ uint32_t smem_u32(const void* p) {
    uint32_t a;
    asm("{ .reg .u64 t; cvta.to.shared.u64 t, %1; cvt.u32.u64 %0, t; }"
        : "=r"(a) : "l"(p));
    return a;
}

__device__ __forceinline__ void ldmatrix_x4(uint32_t* r, uint32_t addr) {
    asm volatile("ldmatrix.sync.aligned.m8n8.x4.shared.b16 {%0,%1,%2,%3}, [%4];"
        : "=r"(r[0]), "=r"(r[1]), "=r"(r[2]), "=r"(r[3]) : "r"(addr));
}

__device__ __forceinline__ void mma_bf16(float* d, const uint32_t* a, const uint32_t* b) {
    asm volatile(
        "mma.sync.aligned.m16n8k16.row.col.f32.bf16.bf16.f32 "
        "{%0,%1,%2,%3}, {%4,%5,%6,%7}, {%8,%9}, {%0,%1,%2,%3};"
        : "+f"(d[0]), "+f"(d[1]), "+f"(d[2]), "+f"(d[3])
        : "r"(a[0]), "r"(a[1]), "r"(a[2]), "r"(a[3]), "r"(b[0]), "r"(b[1]));
}

// ---------------- init: zero cnt + colsum in one kernel ----------------
__global__ void k_zero_init() {
    int i = blockIdx.x * blockDim.x + threadIdx.x;
    if (i < N_NODES) g_cnt[i] = 0;
    if (i < F) g_colsum[i] = 0.0f;
}

// ---------------- CSR build ------------------------------------------------
__global__ void k_hist(const int* __restrict__ er) {
    int i = blockIdx.x * blockDim.x + threadIdx.x;
    if (i < E_EDGES) atomicAdd(&g_cnt[er[i]], 1);
}

__device__ __forceinline__ int warp_scan_incl(int v, int lane) {
    #pragma unroll
    for (int off = 1; off < 32; off <<= 1) {
        int t = __shfl_up_sync(0xffffffffu, v, off);
        if (lane >= off) v += t;
    }
    return v;
}

__global__ void k_scan1() {
    __shared__ int wsum[8];
    int t = threadIdx.x;
    int lane = t & 31, wid = t >> 5;
    int i = blockIdx.x * SCAN_BLK + t;
    int v = (i < N_NODES) ? g_cnt[i] : 0;
    int incl = warp_scan_incl(v, lane);
    if (lane == 31) wsum[wid] = incl;
    __syncthreads();
    if (wid == 0) {
        int s = (lane < 8) ? wsum[lane] : 0;
        s = warp_scan_incl(s, lane);
        if (lane < 8) wsum[lane] = s;
    }
    __syncthreads();
    int off = wid ? wsum[wid - 1] : 0;
    incl += off;
    if (i < N_NODES) g_rowptr[i] = incl - v;
    if (t == SCAN_BLK - 1) g_bsum[blockIdx.x] = incl;
}

__global__ void k_scan2() {
    __shared__ int wsum[16];
    int t = threadIdx.x;
    int lane = t & 31, wid = t >> 5;
    int v = (t < SCAN_NBLK) ? g_bsum[t] : 0;
    int incl = warp_scan_incl(v, lane);
    if (lane == 31) wsum[wid] = incl;
    __syncthreads();
    if (wid == 0) {
        int s = (lane < 16) ? wsum[lane] : 0;
        s = warp_scan_incl(s, lane);
        if (lane < 16) wsum[lane] = s;
    }
    __syncthreads();
    int off = wid ? wsum[wid - 1] : 0;
    incl += off;
    if (t < SCAN_NBLK) g_boff[t] = incl - v;
}

__global__ void k_scan3() {
    int i = blockIdx.x * blockDim.x + threadIdx.x;
    if (i < N_NODES) {
        int val = g_rowptr[i] + g_boff[i >> 8];
        g_rowptr[i] = val;
        g_cnt[i] = val;
    }
    if (i == 0) g_rowptr[N_NODES] = E_EDGES;
}

__global__ void k_scatter(const int* __restrict__ er, const int* __restrict__ ec,
                          const float* __restrict__ ev) {
    int i = blockIdx.x * blockDim.x + threadIdx.x;
    if (i < E_EDGES) {
        int row = er[i];
        int pos = atomicAdd(&g_cnt[row], 1);
        g_csr_col[pos] = ec[i];
        g_csr_val[pos] = ev[i];
    }
}

// ---------------- weight transpose + bf16 split ---------------------------
__global__ void k_wsplit(const float* __restrict__ W, int wid4)
{
    int i = blockIdx.x * blockDim.x + threadIdx.x;
    if (i >= F * F) return;
    int n = i >> 8, k = i & 255;
    float x = W[k * F + n];
    __nv_bfloat16 h = __float2bfloat16(x);
    g_Wt1[wid4 * F * F + i] = h;
    g_Wt2[wid4 * F * F + i] = __float2bfloat16(x - __bfloat162float(h));
}

// ---------------- fused-split mma.sync dual GEMM ---------------------------
__global__ __launch_bounds__(256, 2) void k_gemm_fused(
    const float* __restrict__ Asrc, const float* __restrict__ rvec,
    const __nv_bfloat16* __restrict__ Ws1, const __nv_bfloat16* __restrict__ Ws2,
    const __nv_bfloat16* __restrict__ Wn1, const __nv_bfloat16* __restrict__ Wn2,
    const float* __restrict__ bias,
    float* __restrict__ Cs, __half* __restrict__ Sn, int M)
{
    extern __shared__ __align__(16) char smem[];

    const int tid  = threadIdx.x;
    const int wid  = tid >> 5;
    const int lane = tid & 31;
    const int rowBlock = blockIdx.x * 128;
    const int nBlock   = blockIdx.y * 64;
    const int grp = wid >> 2;            // 0 = self, 1 = nb
    const int wm  = (wid & 3) * 32;

    const uint32_t sA1u = smem_u32(smem);
    const uint32_t sA2u = sA1u + 16384;
    const uint32_t B1u  = sA1u + 32768 + (grp ? 8192 : 0);
    const uint32_t B2u  = sA1u + 49152 + (grp ? 8192 : 0);

    float acc[2][8][4];
    #pragma unroll
    for (int mi = 0; mi < 2; mi++)
        #pragma unroll
        for (int ni = 0; ni < 8; ni++)
            #pragma unroll
            for (int q = 0; q < 4; q++) acc[mi][ni][q] = 0.0f;

    const int aRow = (lane & 15);
    const int aKc  = (lane >> 4) << 3;
    const int bN   = ((lane >> 4) & 1) * 8 + (lane & 7);
    const int bKc  = ((lane >> 3) & 1) * 8;

    #pragma unroll 1
    for (int k0 = 0; k0 < F; k0 += 64) {
        #pragma unroll
        for (int it = 0; it < 8; it++) {
            int idx = tid + it * 256;
            int r   = idx >> 4;
            int c4  = idx & 15;
            int grow = rowBlock + r;
            float4 v = make_float4(0.f, 0.f, 0.f, 0.f);
            if (grow < M) {
                v = *reinterpret_cast<const float4*>(Asrc + (size_t)grow * F + k0 + c4 * 4);
                if (rvec) {
                    float rr = rvec[grow];
                    v.x *= rr; v.y *= rr; v.z *= rr; v.w *= rr;
                }
            }
            __nv_bfloat162 h01 = __floats2bfloat162_rn(v.x, v.y);
            __nv_bfloat162 h23 = __floats2bfloat162_rn(v.z, v.w);
            float2 f01 = __bfloat1622float2(h01);
            float2 f23 = __bfloat1622float2(h23);
            __nv_bfloat162 l01 = __floats2bfloat162_rn(v.x - f01.x, v.y - f01.y);
            __nv_bfloat162 l23 = __floats2bfloat162_rn(v.z - f23.x, v.w - f23.y);
            uint32_t off = SMEM_SWIZZLE_128B((uint32_t)(r * 128 + c4 * 8));
            uint2 hi, lo;
            hi.x = *reinterpret_cast<uint32_t*>(&h01);
            hi.y = *reinterpret_cast<uint32_t*>(&h23);
            lo.x = *reinterpret_cast<uint32_t*>(&l01);
            lo.y = *reinterpret_cast<uint32_t*>(&l23);
            *reinterpret_cast<uint2*>(smem + off)         = hi;
            *reinterpret_cast<uint2*>(smem + 16384 + off) = lo;
        }
        #pragma unroll
        for (int t = 0; t < 4; t++) {
            const __nv_bfloat16* Wp = (t == 0) ? Ws1 : (t == 1) ? Wn1 : (t == 2) ? Ws2 : Wn2;
            char* dst = smem + 32768 + t * 8192;
            #pragma unroll
            for (int it = 0; it < 2; it++) {
                int idx = tid + it * 256;
                int r = idx >> 3, c = idx & 7;
                uint32_t off = SMEM_SWIZZLE_128B((uint32_t)(r * 128 + c * 16));
                *reinterpret_cast<uint4*>(dst + off) =
                    *reinterpret_cast<const uint4*>(Wp + (size_t)(nBlock + r) * F + k0 + c * 8);
            }
        }
        __syncthreads();

        #pragma unroll 1
        for (int combo = 0; combo < 3; combo++) {
            const uint32_t Au = (combo == 1) ? sA2u : sA1u;
            const uint32_t Bu = (combo == 2) ? B2u  : B1u;
            #pragma unroll
            for (int kk = 0; kk < 64; kk += 16) {
                uint32_t a[2][4];
                #pragma unroll
                for (int mi = 0; mi < 2; mi++) {
                    int row = wm + mi * 16 + aRow;
                    ldmatrix_x4(a[mi], Au +
                        SMEM_SWIZZLE_128B((uint32_t)(row * 128 + (kk + aKc) * 2)));
                }
                uint32_t b[8][2];
                #pragma unroll
                for (int np = 0; np < 4; np++) {
                    uint32_t r4[4];
                    int n = np * 16 + bN;
                    ldmatrix_x4(r4, Bu +
                        SMEM_SWIZZLE_128B((uint32_t)(n * 128 + (kk + bKc) * 2)));
                    b[np * 2][0]     = r4[0];
                    b[np * 2][1]     = r4[1];
                    b[np * 2 + 1][0] = r4[2];
                    b[np * 2 + 1][1] = r4[3];
                }
                #pragma unroll
                for (int mi = 0; mi < 2; mi++)
                    #pragma unroll
                    for (int ni = 0; ni < 8; ni++)
                        mma_bf16(acc[mi][ni], a[mi], b[ni]);
            }
        }
        __syncthreads();
    }

    const int rq = lane >> 2;
    const int cq = (lane & 3) * 2;
    if (grp == 0) {
        #pragma unroll
        for (int mi = 0; mi < 2; mi++) {
            #pragma unroll
            for (int ni = 0; ni < 8; ni++) {
                int n = nBlock + ni * 8 + cq;
                float b0 = bias[n], b1 = bias[n + 1];
                int m0 = rowBlock + wm + mi * 16 + rq;
                if (m0 < M)
                    *reinterpret_cast<float2*>(Cs + (size_t)m0 * F + n) =
                        make_float2(acc[mi][ni][0] + b0, acc[mi][ni][1] + b1);
                int m1 = m0 + 8;
                if (m1 < M)
                    *reinterpret_cast<float2*>(Cs + (size_t)m1 * F + n) =
                        make_float2(acc[mi][ni][2] + b0, acc[mi][ni][3] + b1);
            }
        }
    } else {
        #pragma unroll
        for (int mi = 0; mi < 2; mi++) {
            #pragma unroll
            for (int ni = 0; ni < 8; ni++) {
                int n = nBlock + ni * 8 + cq;
                int m0 = rowBlock + wm + mi * 16 + rq;
                if (m0 < M)
                    *reinterpret_cast<__half2*>(Sn + (size_t)m0 * F + n) =
                        __floats2half2_rn(acc[mi][ni][0], acc[mi][ni][1]);
                int m1 = m0 + 8;
                if (m1 < M)
                    *reinterpret_cast<__half2*>(Sn + (size_t)m1 * F + n) =
                        __floats2half2_rn(acc[mi][ni][2], acc[mi][ni][3]);
            }
        }
    }
}

// ---------------- shared SpMM edge-gather core -----------------------------
__device__ __forceinline__ void spmm_row(int s, int e, int lane, float* acc)
{
    const uint4* Sv = reinterpret_cast<const uint4*>(g_Sh);
    #pragma unroll
    for (int j = 0; j < 8; j++) acc[j] = 0.f;

    int i = s;
    for (; i + 3 < e; i += 4) {
        int c0 = g_csr_col[i],     c1 = g_csr_col[i + 1];
        int c2 = g_csr_col[i + 2], c3 = g_csr_col[i + 3];
        float v0 = g_csr_val[i],     v1 = g_csr_val[i + 1];
        float v2 = g_csr_val[i + 2], v3 = g_csr_val[i + 3];
        uint4 q0 = __ldg(Sv + (size_t)c0 * 32 + lane);
        uint4 q1 = __ldg(Sv + (size_t)c1 * 32 + lane);
        uint4 q2 = __ldg(Sv + (size_t)c2 * 32 + lane);
        uint4 q3 = __ldg(Sv + (size_t)c3 * 32 + lane);
        const __half2* h0 = reinterpret_cast<const __half2*>(&q0);
        const __half2* h1 = reinterpret_cast<const __half2*>(&q1);
        const __half2* h2 = reinterpret_cast<const __half2*>(&q2);
        const __half2* h3 = reinterpret_cast<const __half2*>(&q3);
        #pragma unroll
        for (int j = 0; j < 4; j++) {
            float2 f0 = __half22float2(h0[j]);
            float2 f1 = __half22float2(h1[j]);
            float2 f2 = __half22float2(h2[j]);
            float2 f3 = __half22float2(h3[j]);
            acc[2 * j]     += v0 * f0.x + v1 * f1.x + v2 * f2.x + v3 * f3.x;
            acc[2 * j + 1] += v0 * f0.y + v1 * f1.y + v2 * f2.y + v3 * f3.y;
        }
    }
    for (; i < e; i++) {
        int   c0 = g_csr_col[i];
        float v0 = g_csr_val[i];
        uint4 q0 = __ldg(Sv + (size_t)c0 * 32 + lane);
        const __half2* h0 = reinterpret_cast<const __half2*>(&q0);
        #pragma unroll
        for (int j = 0; j < 4; j++) {
            float2 f0 = __half22float2(h0[j]);
            acc[2 * j]     += v0 * f0.x;
            acc[2 * j + 1] += v0 * f0.y;
        }
    }
}

// ---------------- SpMM-1 fused: relu -> X1 + gate dots ---------------------
__global__ __launch_bounds__(256) void k_spmm1(
    const float* __restrict__ w1, const float* __restrict__ b1g,
    const float* __restrict__ w2, const float* __restrict__ b2g)
{
    int warp = (blockIdx.x * blockDim.x + threadIdx.x) >> 5;
    int lane = threadIdx.x & 31;
    if (warp >= N_NODES) return;

    float acc[8];
    spmm_row(g_rowptr[warp], g_rowptr[warp + 1], lane, acc);

    const float* Ap = g_A + (size_t)warp * F + lane * 8;
    float4 b0 = *reinterpret_cast<const float4*>(Ap);
    float4 b1 = *reinterpret_cast<const float4*>(Ap + 4);
    float x[8];
    x[0] = fmaxf(b0.x + acc[0], 0.f); x[1] = fmaxf(b0.y + acc[1], 0.f);
    x[2] = fmaxf(b0.z + acc[2], 0.f); x[3] = fmaxf(b0.w + acc[3], 0.f);
    x[4] = fmaxf(b1.x + acc[4], 0.f); x[5] = fmaxf(b1.y + acc[5], 0.f);
    x[6] = fmaxf(b1.z + acc[6], 0.f); x[7] = fmaxf(b1.w + acc[7], 0.f);

    float* Xp = g_X1 + (size_t)warp * F + lane * 8;
    *reinterpret_cast<float4*>(Xp)     = make_float4(x[0], x[1], x[2], x[3]);
    *reinterpret_cast<float4*>(Xp + 4) = make_float4(x[4], x[5], x[6], x[7]);

    float4 u0 = __ldg(reinterpret_cast<const float4*>(w1 + lane * 8));
    float4 u1 = __ldg(reinterpret_cast<const float4*>(w1 + lane * 8 + 4));
    float4 t0 = __ldg(reinterpret_cast<const float4*>(w2 + lane * 8));
    float4 t1 = __ldg(reinterpret_cast<const float4*>(w2 + lane * 8 + 4));
    float d1 = x[0]*u0.x + x[1]*u0.y + x[2]*u0.z + x[3]*u0.w
             + x[4]*u1.x + x[5]*u1.y + x[6]*u1.z + x[7]*u1.w;
    float d2 = x[0]*t0.x + x[1]*t0.y + x[2]*t0.z + x[3]*t0.w
             + x[4]*t1.x + x[5]*t1.y + x[6]*t1.z + x[7]*t1.w;
    #pragma unroll
    for (int off = 16; off; off >>= 1) {
        d1 += __shfl_xor_sync(0xffffffffu, d1, off);
        d2 += __shfl_xor_sync(0xffffffffu, d2, off);
    }
    if (lane == 0) {
        g_g1[warp] = d1 + b1g[0];
        g_g2[warp] = d2 + b2g[0];
    }
}

// ---------------- SpMM-2 fused: relu, mix, write out, colsum ---------------
#define SPMM2_BLOCKS 1600
__global__ __launch_bounds__(256) void k_spmm2(float* __restrict__ out)
{
    __shared__ float cs[F];
    int tid  = threadIdx.x;
    int lane = tid & 31;
    if (tid < F) cs[tid] = 0.f;
    __syncthreads();

    float local[8];
    #pragma unroll
    for (int j = 0; j < 8; j++) local[j] = 0.f;

    int warpG  = (blockIdx.x * blockDim.x + tid) >> 5;
    int nWarps = SPMM2_BLOCKS * (256 / 32);

    for (int row = warpG; row < N_NODES; row += nWarps) {
        float acc[8];
        spmm_row(g_rowptr[row], g_rowptr[row + 1], lane, acc);

        const float* Ap = g_A + (size_t)row * F + lane * 8;
        float4 b0 = *reinterpret_cast<const float4*>(Ap);
        float4 b1 = *reinterpret_cast<const float4*>(Ap + 4);
        float x2[8];
        x2[0] = fmaxf(b0.x + acc[0], 0.f); x2[1] = fmaxf(b0.y + acc[1], 0.f);
        x2[2] = fmaxf(b0.z + acc[2], 0.f); x2[3] = fmaxf(b0.w + acc[3], 0.f);
        x2[4] = fmaxf(b1.x + acc[4], 0.f); x2[5] = fmaxf(b1.y + acc[5], 0.f);
        x2[6] = fmaxf(b1.z + acc[6], 0.f); x2[7] = fmaxf(b1.w + acc[7], 0.f);

        float z  = g_z[row];
        float iz = 1.f - z;
        const float* Xp = g_X1 + (size_t)row * F + lane * 8;
        float4 x10 = *reinterpret_cast<const float4*>(Xp);
        float4 x11 = *reinterpret_cast<const float4*>(Xp + 4);
        float xe[8];
        xe[0] = iz * x10.x + z * x2[0]; xe[1] = iz * x10.y + z * x2[1];
        xe[2] = iz * x10.z + z * x2[2]; xe[3] = iz * x10.w + z * x2[3];
        xe[4] = iz * x11.x + z * x2[4]; xe[5] = iz * x11.y + z * x2[5];
        xe[6] = iz * x11.z + z * x2[6]; xe[7] = iz * x11.w + z * x2[7];

        float* Op = out + (size_t)row * F + lane * 8;
        *reinterpret_cast<float4*>(Op)     = make_float4(xe[0], xe[1], xe[2], xe[3]);
        *reinterpret_cast<float4*>(Op + 4) = make_float4(xe[4], xe[5], xe[6], xe[7]);

        #pragma unroll
        for (int j = 0; j < 8; j++) local[j] += xe[j];
    }

    #pragma unroll
    for (int j = 0; j < 8; j++)
        atomicAdd(&cs[lane * 8 + j], local[j]);
    __syncthreads();
    if (tid < F) atomicAdd(&g_colsum[tid], cs[tid]);
}

// ---------------- softmax over nodes: online (max, sumexp) -----------------
__device__ __forceinline__ void merge_ms(float& m, float& s, float mb, float sb) {
    float M = fmaxf(m, mb);
    s = s * __expf(m - M) + sb * __expf(mb - M);
    m = M;
}

__global__ void k_softmax_part()
{
    float m1 = NEG_BIG, s1 = 0.f, m2 = NEG_BIG, s2 = 0.f;
    for (int i = blockIdx.x * blockDim.x + threadIdx.x; i < N_NODES;
         i += gridDim.x * blockDim.x) {
        float v1 = g_g1[i];
        merge_ms(m1, s1, v1, 1.0f);
        float v2 = g_g2[i];
        merge_ms(m2, s2, v2, 1.0f);
    }
    __shared__ float sm1[256], ss1[256], sm2[256], ss2[256];
    int t = threadIdx.x;
    sm1[t] = m1; ss1[t] = s1; sm2[t] = m2; ss2[t] = s2;
    __syncthreads();
    for (int off = 128; off; off >>= 1) {
        if (t < off) {
            float mm = sm1[t], ss = ss1[t];
            merge_ms(mm, ss, sm1[t + off], ss1[t + off]);
            sm1[t] = mm; ss1[t] = ss;
            mm = sm2[t]; ss = ss2[t];
            merge_ms(mm, ss, sm2[t + off], ss2[t + off]);
            sm2[t] = mm; ss2[t] = ss;
        }
        __syncthreads();
    }
    if (t == 0) {
        g_part[blockIdx.x * 4 + 0] = sm1[0];
        g_part[blockIdx.x * 4 + 1] = ss1[0];
        g_part[blockIdx.x * 4 + 2] = sm2[0];
        g_part[blockIdx.x * 4 + 3] = ss2[0];
    }
}

__global__ void k_softmax_final(int nparts)
{
    __shared__ float sm1[128], ss1[128], sm2[128], ss2[128];
    int t = threadIdx.x;
    float m1 = NEG_BIG, s1 = 0.f, m2 = NEG_BIG, s2 = 0.f;
    if (t < nparts) {
        m1 = g_part[t * 4 + 0]; s1 = g_part[t * 4 + 1];
        m2 = g_part[t * 4 + 2]; s2 = g_part[t * 4 + 3];
    }
    sm1[t] = m1; ss1[t] = s1; sm2[t] = m2; ss2[t] = s2;
    __syncthreads();
    for (int off = 64; off; off >>= 1) {
        if (t < off) {
            float mm = sm1[t], ss = ss1[t];
            merge_ms(mm, ss, sm1[t + off], ss1[t + off]);
            sm1[t] = mm; ss1[t] = ss;
            mm = sm2[t]; ss = ss2[t];
            merge_ms(mm, ss, sm2[t + off], ss2[t + off]);
            sm2[t] = mm; ss2[t] = ss;
        }
        __syncthreads();
    }
    if (t == 0) {
        g_stat[0] = sm1[0]; g_stat[1] = ss1[0];
        g_stat[2] = sm2[0]; g_stat[3] = ss2[0];
    }
}

__global__ void k_rz()
{
    int i = blockIdx.x * blockDim.x + threadIdx.x;
    if (i < N_NODES) {
        g_r[i] = __expf(g_g1[i] - g_stat[0]) / g_stat[1];
        g_z[i] = __expf(g_g2[i] - g_stat[2]) / g_stat[3];
    }
}

// ---------------- output head ---------------------------------------------
__global__ void k_out(const float* __restrict__ e2pw, const float* __restrict__ e2pb,
                      float* __restrict__ out)
{
    __shared__ float mean[F];
    for (int i = threadIdx.x; i < F; i += blockDim.x)
        mean[i] = g_colsum[i] * (1.0f / N_NODES);
    __syncthreads();
    int j = threadIdx.x;
    if (j < NOUT) {
        float acc = e2pb[j];
        #pragma unroll 8
        for (int k = 0; k < F; k++)
            acc += mean[k] * e2pw[(size_t)k * NOUT + j];
        out[(size_t)N_NODES * F + j] = acc;
    }
}

// ---------------- launch ----------------
extern "C" void kernel_launch(void* const* d_in, const int* in_sizes, int n_in,
                              void* d_out, int out_size)
{
    const float* inputs  = (const float*)d_in[0];
    const int*   er      = (const int*)  d_in[1];
    const int*   ec      = (const int*)  d_in[2];
    const float* ev      = (const float*)d_in[3];
    const float* W_self1 = (const float*)d_in[4];
    const float* W_nb1   = (const float*)d_in[5];
    const float* b1      = (const float*)d_in[6];
    const float* W_self2 = (const float*)d_in[7];
    const float* W_nb2   = (const float*)d_in[8];
    const float* b2      = (const float*)d_in[9];
    const float* g1w     = (const float*)d_in[10];
    const float* g1b     = (const float*)d_in[11];
    const float* g2w     = (const float*)d_in[12];
    const float* g2b     = (const float*)d_in[13];
    const float* e2pw    = (const float*)d_in[14];
    const float* e2pb    = (const float*)d_in[15];
    float* out = (float*)d_out;

    float *pA, *pX1, *pR;
    __half* pSh;
    cudaGetSymbolAddress((void**)&pA,  g_A);
    cudaGetSymbolAddress((void**)&pX1, g_X1);
    cudaGetSymbolAddress((void**)&pR,  g_r);
    cudaGetSymbolAddress((void**)&pSh, g_Sh);
    __nv_bfloat16 *pWt1, *pWt2;
    cudaGetSymbolAddress((void**)&pWt1, g_Wt1);
    cudaGetSymbolAddress((void**)&pWt2, g_Wt2);

    const int SMEM_GEMM = 65536;
    cudaFuncSetAttribute(k_gemm_fused, cudaFuncAttributeMaxDynamicSharedMemorySize, SMEM_GEMM);

    const int EB = (E_EDGES + 255) / 256;
    const int NB = (N_NODES + 255) / 256;
    dim3 gmm((N_NODES + 127) / 128, 4);

    // ---- CSR build + init ----
    k_zero_init<<<NB, 256>>>();
    k_hist<<<EB, 256>>>(er);
    k_scan1<<<SCAN_NBLK, SCAN_BLK>>>();
    k_scan2<<<1, 512>>>();
    k_scan3<<<NB, 256>>>();
    k_scatter<<<EB, 256>>>(er, ec, ev);

    // ---- weight transpose + bf16 split ----
    k_wsplit<<<(F * F + 255) / 256, 256>>>(W_self1, 0);
    k_wsplit<<<(F * F + 255) / 256, 256>>>(W_nb1,   1);
    k_wsplit<<<(F * F + 255) / 256, 256>>>(W_self2, 2);
    k_wsplit<<<(F * F + 255) / 256, 256>>>(W_nb2,   3);

    // ---- layer 1 ----
    k_gemm_fused<<<gmm, 256, SMEM_GEMM>>>(inputs, nullptr,
                             pWt1 + 0 * F * F, pWt2 + 0 * F * F,
                             pWt1 + 1 * F * F, pWt2 + 1 * F * F,
                             b1, pA, pSh, N_NODES);
    k_spmm1<<<(N_NODES * 32 + 255) / 256, 256>>>(g1w, g1b, g2w, g2b);

    // ---- softmax gates over nodes ----
    k_softmax_part<<<120, 256>>>();
    k_softmax_final<<<1, 128>>>(120);
    k_rz<<<NB, 256>>>();

    // ---- layer 2 ----
    k_gemm_fused<<<gmm, 256, SMEM_GEMM>>>(pX1, pR,
                             pWt1 + 2 * F * F, pWt2 + 2 * F * F,
                             pWt1 + 3 * F * F, pWt2 + 3 * F * F,
                             b2, pA, pSh, N_NODES);
    k_spmm2<<<SPMM2_BLOCKS, 256>>>(out);

    // ---- head ----
    k_out<<<1, 128>>>(e2pw, e2pb, out);
}